// round 2
// baseline (speedup 1.0000x reference)
#include <cuda_runtime.h>
#include <cuda_bf16.h>
#include <cstdint>

#define BATCH 64
#define SEQ   256
#define HID   512
#define NTAG  48
#define MROWS (BATCH*SEQ)     // 16384
#define G4    2048            // 4*HID
#define H2    1024            // 2*HID

// ------------------- static device scratch (no allocation allowed) -------------------
__device__ float d_WihP0f[2048*256];
__device__ float d_WihP0b[2048*256];
__device__ float d_WihP1f[2048*1024];
__device__ float d_WihP1b[2048*1024];
__device__ float d_WhhPf0[2048*512];
__device__ float d_WhhPb0[2048*512];
__device__ float d_WhhPf1[2048*512];
__device__ float d_WhhPb1[2048*512];
__device__ float d_biasPf0[2048];
__device__ float d_biasPb0[2048];
__device__ float d_biasPf1[2048];
__device__ float d_biasPb1[2048];
__device__ float d_pref[16384*2048];
__device__ float d_preb[16384*2048];
__device__ float d_x1[16384*1024];
__device__ float d_x2[16384*1024];
__device__ float d_f1[16384*512];
__device__ float d_f2[16384*256];
__device__ float d_em[16384*48];
__device__ float d_hbuf[2*2*BATCH*HID];   // [parity][dir][b][j]
__device__ float d_v[64];

__device__ unsigned g_cnt;
__device__ volatile unsigned g_gen;

// ------------------- helpers -------------------
__device__ __forceinline__ unsigned f2tf(float x){
    unsigned r;
    asm("cvt.rna.tf32.f32 %0, %1;" : "=r"(r) : "f"(x));
    return r;
}

__device__ __forceinline__ void mma8(float* c, const unsigned* a, const unsigned* b){
    asm volatile(
        "mma.sync.aligned.m16n8k8.row.col.f32.tf32.tf32.f32 "
        "{%0,%1,%2,%3}, {%4,%5,%6,%7}, {%8,%9}, {%0,%1,%2,%3};\n"
        : "+f"(c[0]), "+f"(c[1]), "+f"(c[2]), "+f"(c[3])
        : "r"(a[0]), "r"(a[1]), "r"(a[2]), "r"(a[3]),
          "r"(b[0]), "r"(b[1]));
}

__device__ __forceinline__ void grid_barrier(){
    __syncthreads();
    if (threadIdx.x == 0){
        __threadfence();
        unsigned gen = g_gen;
        if (atomicAdd(&g_cnt, 1u) == gridDim.x - 1){
            g_cnt = 0;
            __threadfence();
            g_gen = gen + 1;
        } else {
            while (g_gen == gen) { }
        }
    }
    __syncthreads();
}

// ------------------- weight prep -------------------
// gate-interleaved permutation: out row n' -> src row (n'&3)*512 + (n'>>2)
__global__ void permute_w(const float* __restrict__ src, float* __restrict__ dst, int K){
    int total = 2048 * K;
    for (int i = blockIdx.x*blockDim.x + threadIdx.x; i < total; i += gridDim.x*blockDim.x){
        int np = i / K;
        int k  = i - np*K;
        int sr = (np & 3)*512 + (np >> 2);
        dst[i] = src[sr*K + k];
    }
}

__global__ void bias_comb(const float* __restrict__ bih, const float* __restrict__ bhh,
                          float* __restrict__ dst){
    int np = blockIdx.x*blockDim.x + threadIdx.x;
    if (np < 2048){
        int sr = (np & 3)*512 + (np >> 2);
        dst[np] = bih[sr] + bhh[sr];
    }
}

__global__ void zero_h_kernel(){
    int i = blockIdx.x*blockDim.x + threadIdx.x;
    if (i == 0){ g_cnt = 0; g_gen = 0; }
    for (int q = i; q < 2*2*BATCH*HID; q += gridDim.x*blockDim.x) d_hbuf[q] = 0.f;
}

// ------------------- generic tf32 GEMM:  C = A(MxK) @ W(NxK)^T + bias, opt relu ----------
#define TSD 36
__device__ __forceinline__ void gm_fetch(const float* __restrict__ A, const float* __restrict__ W,
                                         int N, int K, int m0, int n0, int kt, int tid,
                                         float4* ra, float4* rb){
#pragma unroll
    for (int i = 0; i < 4; i++){
        int q = i*256 + tid;
        int r = q >> 3;
        int c = (q & 7) * 4;
        ra[i] = *(const float4*)&A[(m0 + r)*K + kt*32 + c];
        int nr = n0 + r;
        if (nr < N) rb[i] = *(const float4*)&W[nr*K + kt*32 + c];
        else        rb[i] = make_float4(0.f,0.f,0.f,0.f);
    }
}

__device__ __forceinline__ void sm_store(float* As, float* Bs, int bb, int tid,
                                         const float4* ra, const float4* rb){
#pragma unroll
    for (int i = 0; i < 4; i++){
        int q = i*256 + tid;
        int r = q >> 3;
        int c = (q & 7) * 4;
        float4 t;
        t.x = __uint_as_float(f2tf(ra[i].x));
        t.y = __uint_as_float(f2tf(ra[i].y));
        t.z = __uint_as_float(f2tf(ra[i].z));
        t.w = __uint_as_float(f2tf(ra[i].w));
        *(float4*)&As[bb*128*TSD + r*TSD + c] = t;
        t.x = __uint_as_float(f2tf(rb[i].x));
        t.y = __uint_as_float(f2tf(rb[i].y));
        t.z = __uint_as_float(f2tf(rb[i].z));
        t.w = __uint_as_float(f2tf(rb[i].w));
        *(float4*)&Bs[bb*128*TSD + r*TSD + c] = t;
    }
}

__global__ __launch_bounds__(256) void gemm_tf32(
    const float* __restrict__ A, const float* __restrict__ W,
    const float* __restrict__ bias, float* __restrict__ C,
    int M, int N, int K, int relu)
{
    extern __shared__ float sm[];
    float* As = sm;
    float* Bs = sm + 2*128*TSD;
    int tid  = threadIdx.x;
    int warp = tid >> 5, lane = tid & 31;
    int wm = warp >> 2, wn = warp & 3;
    int g = lane >> 2, tg = lane & 3;
    int m0 = blockIdx.y*128, n0 = blockIdx.x*128;

    float acc[4][4][4];
#pragma unroll
    for (int a = 0; a < 4; a++)
#pragma unroll
        for (int b = 0; b < 4; b++)
#pragma unroll
            for (int c = 0; c < 4; c++) acc[a][b][c] = 0.f;

    int KT = K >> 5;
    float4 ra[4], rb[4];
    gm_fetch(A, W, N, K, m0, n0, 0, tid, ra, rb);
    sm_store(As, Bs, 0, tid, ra, rb);
    __syncthreads();

    for (int kt = 0; kt < KT; kt++){
        int bb = kt & 1;
        if (kt + 1 < KT) gm_fetch(A, W, N, K, m0, n0, kt+1, tid, ra, rb);

        const float* Ab = As + bb*128*TSD + wm*64*TSD;
        const float* Bb = Bs + bb*128*TSD + wn*32*TSD;
#pragma unroll
        for (int kk = 0; kk < 4; kk++){
            int kc = kk*8;
            unsigned af[4][4], bf[4][2];
#pragma unroll
            for (int mt = 0; mt < 4; mt++){
                const float* p = Ab + mt*16*TSD + kc;
                af[mt][0] = __float_as_uint(p[g*TSD + tg]);
                af[mt][1] = __float_as_uint(p[(g+8)*TSD + tg]);
                af[mt][2] = __float_as_uint(p[g*TSD + tg + 4]);
                af[mt][3] = __float_as_uint(p[(g+8)*TSD + tg + 4]);
            }
#pragma unroll
            for (int nt = 0; nt < 4; nt++){
                const float* p = Bb + nt*8*TSD + kc;
                bf[nt][0] = __float_as_uint(p[g*TSD + tg]);
                bf[nt][1] = __float_as_uint(p[g*TSD + tg + 4]);
            }
#pragma unroll
            for (int mt = 0; mt < 4; mt++)
#pragma unroll
                for (int nt = 0; nt < 4; nt++)
                    mma8(acc[mt][nt], af[mt], bf[nt]);
        }
        if (kt + 1 < KT) sm_store(As, Bs, (kt+1)&1, tid, ra, rb);
        __syncthreads();
    }

#pragma unroll
    for (int mt = 0; mt < 4; mt++){
        int row = m0 + wm*64 + mt*16 + g;
#pragma unroll
        for (int nt = 0; nt < 4; nt++){
            int col = n0 + wn*32 + nt*8 + 2*tg;
            if (col < N){
                float b0 = bias[col], b1 = bias[col+1];
                float v0 = acc[mt][nt][0] + b0;
                float v1 = acc[mt][nt][1] + b1;
                float v2 = acc[mt][nt][2] + b0;
                float v3 = acc[mt][nt][3] + b1;
                if (relu){
                    v0 = fmaxf(v0, 0.f); v1 = fmaxf(v1, 0.f);
                    v2 = fmaxf(v2, 0.f); v3 = fmaxf(v3, 0.f);
                }
                *(float2*)&C[row*N + col]     = make_float2(v0, v1);
                *(float2*)&C[(row+8)*N + col] = make_float2(v2, v3);
            }
        }
    }
}

// ------------------- persistent bidirectional LSTM layer -------------------
// grid = 64 blocks: dir = bx>>5 (0 fwd, 1 bwd), ns = bx&31 -> gate cols [ns*64, ns*64+64)
// (gate-permuted), hidden units [ns*16, ns*16+16). 128 threads.
#define WHS 516
#define HSS 68
__global__ __launch_bounds__(128) void lstm_layer(
    const float* __restrict__ pre_f, const float* __restrict__ pre_b,
    const float* __restrict__ whhF, const float* __restrict__ whhB,
    float* __restrict__ out)
{
    extern __shared__ float sm[];
    float* whh_s = sm;                      // [64][516]
    float* h_s   = whh_s + 64*WHS;          // [64][68]
    float* G_s   = h_s + 64*HSS;            // [64][68]
    float* c_s   = G_s + 64*HSS;            // [64][16]

    int tid = threadIdx.x;
    int warp = tid >> 5, lane = tid & 31;
    int wm = warp >> 1, wn = warp & 1;      // warps 2x2, warp tile 32x32
    int g = lane >> 2, tg = lane & 3;
    int dir = blockIdx.x >> 5;
    int ns  = blockIdx.x & 31;
    int n0  = ns*64;
    int j0  = ns*16;
    const float* whh = dir ? whhB : whhF;
    const float* pre = dir ? pre_b : pre_f;

    // fill persistent Whh slice (tf32)
    for (int q = tid; q < 64*128; q += 128){
        int r = q >> 7;
        int c = (q & 127)*4;
        float4 v = *(const float4*)&whh[(n0 + r)*512 + c];
        float4 t;
        t.x = __uint_as_float(f2tf(v.x));
        t.y = __uint_as_float(f2tf(v.y));
        t.z = __uint_as_float(f2tf(v.z));
        t.w = __uint_as_float(f2tf(v.w));
        *(float4*)&whh_s[r*WHS + c] = t;
    }
    for (int q = tid; q < 64*16; q += 128) c_s[q] = 0.f;
    __syncthreads();

    for (int s = 0; s < SEQ; s++){
        int t  = dir ? (SEQ-1 - s) : s;
        int rp = s & 1;
        int wp = rp ^ 1;
        const float* hsrc = d_hbuf + (rp*2 + dir)*BATCH*HID;

        float acc[2][4][4];
#pragma unroll
        for (int a = 0; a < 2; a++)
#pragma unroll
            for (int b = 0; b < 4; b++)
#pragma unroll
                for (int c = 0; c < 4; c++) acc[a][b][c] = 0.f;

        for (int kc = 0; kc < 512; kc += 64){
            __syncthreads();
            // stage h chunk (L2-only loads: h written by other SMs)
            for (int q = tid; q < 64*16; q += 128){
                int r = q >> 4;
                int c = (q & 15)*4;
                float4 v = __ldcg((const float4*)&hsrc[r*512 + kc + c]);
                float4 tt;
                tt.x = __uint_as_float(f2tf(v.x));
                tt.y = __uint_as_float(f2tf(v.y));
                tt.z = __uint_as_float(f2tf(v.z));
                tt.w = __uint_as_float(f2tf(v.w));
                *(float4*)&h_s[r*HSS + c] = tt;
            }
            __syncthreads();

            const float* Aw = h_s + wm*32*HSS;
            const float* Bw = whh_s + wn*32*WHS + kc;
#pragma unroll
            for (int k8 = 0; k8 < 8; k8++){
                int kcol = k8*8;
                unsigned af[2][4], bf[4][2];
#pragma unroll
                for (int mt = 0; mt < 2; mt++){
                    const float* p = Aw + mt*16*HSS + kcol;
                    af[mt][0] = __float_as_uint(p[g*HSS + tg]);
                    af[mt][1] = __float_as_uint(p[(g+8)*HSS + tg]);
                    af[mt][2] = __float_as_uint(p[g*HSS + tg + 4]);
                    af[mt][3] = __float_as_uint(p[(g+8)*HSS + tg + 4]);
                }
#pragma unroll
                for (int nt = 0; nt < 4; nt++){
                    const float* p = Bw + nt*8*WHS + kcol;
                    bf[nt][0] = __float_as_uint(p[g*WHS + tg]);
                    bf[nt][1] = __float_as_uint(p[g*WHS + tg + 4]);
                }
#pragma unroll
                for (int mt = 0; mt < 2; mt++)
#pragma unroll
                    for (int nt = 0; nt < 4; nt++)
                        mma8(acc[mt][nt], af[mt], bf[nt]);
            }
        }

        // dump accumulators to G_s
#pragma unroll
        for (int mt = 0; mt < 2; mt++){
            int rr = wm*32 + mt*16 + g;
#pragma unroll
            for (int nt = 0; nt < 4; nt++){
                int cc = wn*32 + nt*8 + 2*tg;
                G_s[rr*HSS + cc]       = acc[mt][nt][0];
                G_s[rr*HSS + cc + 1]   = acc[mt][nt][1];
                G_s[(rr+8)*HSS + cc]   = acc[mt][nt][2];
                G_s[(rr+8)*HSS + cc+1] = acc[mt][nt][3];
            }
        }
        __syncthreads();

        // gate update for this block's 16 hidden units x 64 batches
        float* hdst = d_hbuf + (wp*2 + dir)*BATCH*HID;
        for (int q = tid; q < 1024; q += 128){
            int b = q >> 4;
            int u = q & 15;
            float4 Gv = *(float4*)&G_s[b*HSS + 4*u];
            float4 Pv = *(const float4*)&pre[(b*SEQ + t)*G4 + n0 + 4*u];
            float iv = Gv.x + Pv.x;
            float fv = Gv.y + Pv.y;
            float gv = Gv.z + Pv.z;
            float ov = Gv.w + Pv.w;
            float co = c_s[b*16 + u];
            float si = 1.f/(1.f + __expf(-iv));
            float sf = 1.f/(1.f + __expf(-fv));
            float so = 1.f/(1.f + __expf(-ov));
            float cn = sf*co + si*tanhf(gv);
            float hv = so*tanhf(cn);
            c_s[b*16 + u] = cn;
            hdst[b*HID + j0 + u] = hv;
            out[(b*SEQ + t)*H2 + dir*HID + j0 + u] = hv;
        }
        grid_barrier();
    }
}

// ------------------- batchnorm (inference) -------------------
__global__ void bn_kernel(const float* __restrict__ in, float* __restrict__ outp,
                          const float* __restrict__ gamma, const float* __restrict__ beta,
                          const float* __restrict__ mean, const float* __restrict__ var)
{
    int total = MROWS*H2;
    for (int i = blockIdx.x*blockDim.x + threadIdx.x; i < total; i += gridDim.x*blockDim.x){
        int c = i & (H2-1);
        outp[i] = (in[i] - mean[c]) * (gamma[c]*rsqrtf(var[c] + 1e-5f)) + beta[c];
    }
}

// ------------------- CRF: one block per batch -------------------
__global__ void crf_kernel(const float* __restrict__ em, const int* __restrict__ tags,
                           const float* __restrict__ start, const float* __restrict__ endv,
                           const float* __restrict__ trans, float* __restrict__ v)
{
    __shared__ float tr[NTAG*49];
    __shared__ float al[2][NTAG];
    __shared__ float red[64];
    __shared__ float num_s;
    int b = blockIdx.x;
    int tid = threadIdx.x;
    const int* tg = tags + b*SEQ;
    const float* eb = em + b*SEQ*NTAG;

    for (int q = tid; q < NTAG*NTAG; q += 64){
        int i = q / NTAG, j = q - i*NTAG;
        tr[i*49 + j] = trans[q];
    }
    // numerator partial sums
    float part = 0.f;
    for (int t = tid; t < SEQ; t += 64){
        int tt = tg[t];
        part += eb[t*NTAG + tt];
        if (t < SEQ-1) part += trans[tt*NTAG + tg[t+1]];
    }
    red[tid] = part;
    if (tid < NTAG) al[0][tid] = start[tid] + eb[tid];
    __syncthreads();
    if (tid == 0){
        float s = 0.f;
        for (int i = 0; i < 64; i++) s += red[i];
        num_s = s + start[tg[0]] + endv[tg[SEQ-1]];
    }
    __syncthreads();

    for (int t = 1; t < SEQ; t++){
        int cur = t & 1, prv = cur ^ 1;
        float na = 0.f;
        if (tid < NTAG){
            float m = -1e30f;
            for (int i = 0; i < NTAG; i++) m = fmaxf(m, al[prv][i] + tr[i*49 + tid]);
            float ssum = 0.f;
            for (int i = 0; i < NTAG; i++) ssum += __expf(al[prv][i] + tr[i*49 + tid] - m);
            na = m + logf(ssum) + eb[t*NTAG + tid];
        }
        __syncthreads();
        if (tid < NTAG) al[cur][tid] = na;
        __syncthreads();
    }

    if (tid == 0){
        const float* a = al[(SEQ-1) & 1];
        float m = -1e30f;
        for (int j = 0; j < NTAG; j++) m = fmaxf(m, a[j] + endv[j]);
        float s = 0.f;
        for (int j = 0; j < NTAG; j++) s += __expf(a[j] + endv[j] - m);
        float logZ = m + logf(s);
        v[b] = num_s - logZ;
    }
}

__global__ void final_reduce(const float* __restrict__ v, float* __restrict__ out){
    __shared__ float s[64];
    s[threadIdx.x] = v[threadIdx.x];
    __syncthreads();
    if (threadIdx.x == 0){
        float a = 0.f;
        for (int i = 0; i < 64; i++) a += s[i];
        out[0] = -(a / 64.f);
    }
}

// ------------------- launch -------------------
extern "C" void kernel_launch(void* const* d_in, const int* in_sizes, int n_in,
                              void* d_out, int out_size)
{
    const float* inputs = (const float*)d_in[0];
    const int*   tags   = (const int*)d_in[1];
    const float *Wih0f=(const float*)d_in[2],  *Whh0f=(const float*)d_in[3],
                *bih0f=(const float*)d_in[4],  *bhh0f=(const float*)d_in[5];
    const float *Wih0b=(const float*)d_in[6],  *Whh0b=(const float*)d_in[7],
                *bih0b=(const float*)d_in[8],  *bhh0b=(const float*)d_in[9];
    const float *Wih1f=(const float*)d_in[10], *Whh1f=(const float*)d_in[11],
                *bih1f=(const float*)d_in[12], *bhh1f=(const float*)d_in[13];
    const float *Wih1b=(const float*)d_in[14], *Whh1b=(const float*)d_in[15],
                *bih1b=(const float*)d_in[16], *bhh1b=(const float*)d_in[17];
    const float *gamma=(const float*)d_in[18], *beta=(const float*)d_in[19],
                *mean=(const float*)d_in[20],  *var=(const float*)d_in[21];
    const float *fc1w=(const float*)d_in[22], *fc1b=(const float*)d_in[23];
    const float *fc2w=(const float*)d_in[24], *fc2b=(const float*)d_in[25];
    const float *fc3w=(const float*)d_in[26], *fc3b=(const float*)d_in[27];
    const float *crfS=(const float*)d_in[28], *crfE=(const float*)d_in[29],
                *crfT=(const float*)d_in[30];

    float *pWihP0f,*pWihP0b,*pWihP1f,*pWihP1b;
    float *pWhhPf0,*pWhhPb0,*pWhhPf1,*pWhhPb1;
    float *pB0f,*pB0b,*pB1f,*pB1b;
    float *pPref,*pPreb,*pX1,*pX2,*pF1,*pF2,*pEm,*pV;
    cudaGetSymbolAddress((void**)&pWihP0f, d_WihP0f);
    cudaGetSymbolAddress((void**)&pWihP0b, d_WihP0b);
    cudaGetSymbolAddress((void**)&pWihP1f, d_WihP1f);
    cudaGetSymbolAddress((void**)&pWihP1b, d_WihP1b);
    cudaGetSymbolAddress((void**)&pWhhPf0, d_WhhPf0);
    cudaGetSymbolAddress((void**)&pWhhPb0, d_WhhPb0);
    cudaGetSymbolAddress((void**)&pWhhPf1, d_WhhPf1);
    cudaGetSymbolAddress((void**)&pWhhPb1, d_WhhPb1);
    cudaGetSymbolAddress((void**)&pB0f, d_biasPf0);
    cudaGetSymbolAddress((void**)&pB0b, d_biasPb0);
    cudaGetSymbolAddress((void**)&pB1f, d_biasPf1);
    cudaGetSymbolAddress((void**)&pB1b, d_biasPb1);
    cudaGetSymbolAddress((void**)&pPref, d_pref);
    cudaGetSymbolAddress((void**)&pPreb, d_preb);
    cudaGetSymbolAddress((void**)&pX1, d_x1);
    cudaGetSymbolAddress((void**)&pX2, d_x2);
    cudaGetSymbolAddress((void**)&pF1, d_f1);
    cudaGetSymbolAddress((void**)&pF2, d_f2);
    cudaGetSymbolAddress((void**)&pEm, d_em);
    cudaGetSymbolAddress((void**)&pV, d_v);

    cudaFuncSetAttribute(gemm_tf32, cudaFuncAttributeMaxDynamicSharedMemorySize, 2*2*128*TSD*4);
    cudaFuncSetAttribute(lstm_layer, cudaFuncAttributeMaxDynamicSharedMemorySize,
                         (64*WHS + 64*HSS + 64*HSS + 64*16)*4);
    const int gemm_smem = 2*2*128*TSD*4;
    const int lstm_smem = (64*WHS + 64*HSS + 64*HSS + 64*16)*4;

    // ---- weight prep ----
    permute_w<<<1024,256>>>(Wih0f, pWihP0f, 256);
    permute_w<<<1024,256>>>(Wih0b, pWihP0b, 256);
    permute_w<<<2048,256>>>(Wih1f, pWihP1f, 1024);
    permute_w<<<2048,256>>>(Wih1b, pWihP1b, 1024);
    permute_w<<<2048,256>>>(Whh0f, pWhhPf0, 512);
    permute_w<<<2048,256>>>(Whh0b, pWhhPb0, 512);
    permute_w<<<2048,256>>>(Whh1f, pWhhPf1, 512);
    permute_w<<<2048,256>>>(Whh1b, pWhhPb1, 512);
    bias_comb<<<8,256>>>(bih0f, bhh0f, pB0f);
    bias_comb<<<8,256>>>(bih0b, bhh0b, pB0b);
    bias_comb<<<8,256>>>(bih1f, bhh1f, pB1f);
    bias_comb<<<8,256>>>(bih1b, bhh1b, pB1b);

    // ---- layer 0 ----
    gemm_tf32<<<dim3(16,128),256,gemm_smem>>>(inputs, pWihP0f, pB0f, pPref, MROWS, G4, 256, 0);
    gemm_tf32<<<dim3(16,128),256,gemm_smem>>>(inputs, pWihP0b, pB0b, pPreb, MROWS, G4, 256, 0);
    zero_h_kernel<<<64,256>>>();
    lstm_layer<<<64,128,lstm_smem>>>(pPref, pPreb, pWhhPf0, pWhhPb0, pX1);

    // ---- layer 1 ----
    gemm_tf32<<<dim3(16,128),256,gemm_smem>>>(pX1, pWihP1f, pB1f, pPref, MROWS, G4, 1024, 0);
    gemm_tf32<<<dim3(16,128),256,gemm_smem>>>(pX1, pWihP1b, pB1b, pPreb, MROWS, G4, 1024, 0);
    zero_h_kernel<<<64,256>>>();
    lstm_layer<<<64,128,lstm_smem>>>(pPref, pPreb, pWhhPf1, pWhhPb1, pX2);

    // ---- head ----
    bn_kernel<<<4096,256>>>(pX2, pX1, gamma, beta, mean, var);
    gemm_tf32<<<dim3(4,128),256,gemm_smem>>>(pX1, fc1w, fc1b, pF1, MROWS, 512, 1024, 1);
    gemm_tf32<<<dim3(2,128),256,gemm_smem>>>(pF1, fc2w, fc2b, pF2, MROWS, 256, 512, 1);
    gemm_tf32<<<dim3(1,128),256,gemm_smem>>>(pF2, fc3w, fc3b, pEm, MROWS, NTAG, 256, 0);

    // ---- CRF ----
    crf_kernel<<<64,64>>>(pEm, tags, crfS, crfE, crfT, pV);
    final_reduce<<<1,64>>>(pV, (float*)d_out);
}

// round 3
// speedup vs baseline: 2.0039x; 2.0039x over previous
#include <cuda_runtime.h>
#include <cuda_bf16.h>
#include <cstdint>

#define BATCH 64
#define SEQ   256
#define HID   512
#define NTAG  48
#define MROWS (BATCH*SEQ)     // 16384
#define G4    2048
#define H2    1024

// ------------------- static device scratch -------------------
__device__ float d_W0m[4096*256];
__device__ float d_W1m[4096*1024];
__device__ float d_Wh0f[2048*512];
__device__ float d_Wh0b[2048*512];
__device__ float d_Wh1f[2048*512];
__device__ float d_Wh1b[2048*512];
__device__ float d_b0m[4096];
__device__ float d_b1m[4096];
__device__ float d_fc1wP[512*1024];
__device__ float d_fc1bP[512];
__device__ float d_pre[16384*4096];
__device__ float d_x1[16384*1024];
__device__ float d_x2[16384*1024];
__device__ float d_f1[16384*512];
__device__ float d_f2[16384*256];
__device__ float d_em[16384*48];
__device__ float d_hbuf[2*2*BATCH*HID];
__device__ float d_v[64];
__device__ volatile int d_slot[2][32];
__device__ volatile int d_genv[2];

// ------------------- helpers -------------------
__device__ __forceinline__ void mma8(float* c, const unsigned* a, const unsigned* b){
    asm volatile(
        "mma.sync.aligned.m16n8k8.row.col.f32.tf32.tf32.f32 "
        "{%0,%1,%2,%3}, {%4,%5,%6,%7}, {%8,%9}, {%0,%1,%2,%3};\n"
        : "+f"(c[0]), "+f"(c[1]), "+f"(c[2]), "+f"(c[3])
        : "r"(a[0]), "r"(a[1]), "r"(a[2]), "r"(a[3]),
          "r"(b[0]), "r"(b[1]));
}

__device__ __forceinline__ void cp16(void* smem, const void* gmem){
    unsigned sa = (unsigned)__cvta_generic_to_shared(smem);
    asm volatile("cp.async.cg.shared.global [%0], [%1], 16;" :: "r"(sa), "l"(gmem));
}
__device__ __forceinline__ void cp16z(void* smem, const void* gmem, int pred){
    unsigned sa = (unsigned)__cvta_generic_to_shared(smem);
    int bytes = pred ? 16 : 0;
    asm volatile("cp.async.cg.shared.global [%0], [%1], 16, %2;" :: "r"(sa), "l"(gmem), "r"(bytes));
}
__device__ __forceinline__ void cp_commit(){ asm volatile("cp.async.commit_group;"); }
__device__ __forceinline__ void cp_wait0(){ asm volatile("cp.async.wait_group 0;"); }
__device__ __forceinline__ void cp_wait1(){ asm volatile("cp.async.wait_group 1;"); }

// ------------------- prep -------------------
__global__ void prep_all(
    const float* __restrict__ Wih0f, const float* __restrict__ Wih0b,
    const float* __restrict__ Whh0f, const float* __restrict__ Whh0b,
    const float* __restrict__ Wih1f, const float* __restrict__ Wih1b,
    const float* __restrict__ Whh1f, const float* __restrict__ Whh1b,
    const float* __restrict__ bih0f, const float* __restrict__ bhh0f,
    const float* __restrict__ bih0b, const float* __restrict__ bhh0b,
    const float* __restrict__ bih1f, const float* __restrict__ bhh1f,
    const float* __restrict__ bih1b, const float* __restrict__ bhh1b)
{
    const int NW0 = 4096*256;
    const int NW1 = 4096*1024;
    const int NWH = 2048*512;
    const int b1 = NW0;             // W1m
    const int b2 = b1 + NW1;        // Wh0f
    const int b3 = b2 + NWH;        // Wh0b
    const int b4 = b3 + NWH;        // Wh1f
    const int b5 = b4 + NWH;        // Wh1b
    const int b6 = b5 + NWH;        // b0m
    const int b7 = b6 + 4096;       // b1m
    const int b8 = b7 + 4096;       // control
    const int total = b8 + 66;
    int stride = gridDim.x * blockDim.x;
    for (int i = blockIdx.x*blockDim.x + threadIdx.x; i < total; i += stride){
        if (i < NW0){
            int np = i >> 8, k = i & 255;
            int np2 = np & 2047;
            int sr = (np2 & 3)*512 + (np2 >> 2);
            const float* src = (np < 2048) ? Wih0f : Wih0b;
            d_W0m[i] = src[sr*256 + k];
        } else if (i < b2){
            int j = i - b1;
            int np = j >> 10, k = j & 1023;
            int np2 = np & 2047;
            int sr = (np2 & 3)*512 + (np2 >> 2);
            const float* src = (np < 2048) ? Wih1f : Wih1b;
            d_W1m[j] = src[sr*1024 + k];
        } else if (i < b6){
            int j = i - b2;
            int arr = j / NWH;
            int jj = j - arr*NWH;
            int np = jj >> 9, k = jj & 511;
            int sr = (np & 3)*512 + (np >> 2);
            const float* src = (arr==0)?Whh0f:(arr==1)?Whh0b:(arr==2)?Whh1f:Whh1b;
            float* dst = (arr==0)?d_Wh0f:(arr==1)?d_Wh0b:(arr==2)?d_Wh1f:d_Wh1b;
            dst[jj] = src[sr*512 + k];
        } else if (i < b7){
            int np = i - b6;
            int np2 = np & 2047;
            int sr = (np2 & 3)*512 + (np2 >> 2);
            d_b0m[np] = (np < 2048) ? (bih0f[sr] + bhh0f[sr]) : (bih0b[sr] + bhh0b[sr]);
        } else if (i < b8){
            int np = i - b7;
            int np2 = np & 2047;
            int sr = (np2 & 3)*512 + (np2 >> 2);
            d_b1m[np] = (np < 2048) ? (bih1f[sr] + bhh1f[sr]) : (bih1b[sr] + bhh1b[sr]);
        } else {
            int j = i - b8;
            if (j < 64) ((volatile int*)d_slot)[j] = 0;
            else d_genv[j - 64] = 0;
        }
    }
}

// fold BN into fc1: W' = fc1_w * s[c], b' = fc1_b + fc1_w @ t
__global__ void prep_fc(const float* __restrict__ fc1w, const float* __restrict__ fc1b,
                        const float* __restrict__ gamma, const float* __restrict__ beta,
                        const float* __restrict__ mean, const float* __restrict__ var)
{
    __shared__ float red[256];
    int r = blockIdx.x;
    int tid = threadIdx.x;
    float part = 0.f;
    for (int c = tid; c < 1024; c += 256){
        float sc = gamma[c] * rsqrtf(var[c] + 1e-5f);
        float tc = beta[c] - mean[c]*sc;
        float w = fc1w[r*1024 + c];
        d_fc1wP[r*1024 + c] = w * sc;
        part += w * tc;
    }
    red[tid] = part;
    __syncthreads();
    for (int off = 128; off > 0; off >>= 1){
        if (tid < off) red[tid] += red[tid + off];
        __syncthreads();
    }
    if (tid == 0) d_fc1bP[r] = fc1b[r] + red[0];
}

// ------------------- generic tf32 GEMM: C = A(MxK) @ W(NxK)^T + bias, opt relu -------------------
#define TSD 36
__global__ __launch_bounds__(256) void gemm_tf32(
    const float* __restrict__ A, const float* __restrict__ W,
    const float* __restrict__ bias, float* __restrict__ C,
    int M, int N, int K, int relu)
{
    extern __shared__ float sm[];
    float* As = sm;
    float* Bs = sm + 2*128*TSD;
    int tid  = threadIdx.x;
    int warp = tid >> 5, lane = tid & 31;
    int wm = warp >> 2, wn = warp & 3;
    int g = lane >> 2, tg = lane & 3;
    int m0 = blockIdx.y*128, n0 = blockIdx.x*128;

    float acc[4][4][4];
#pragma unroll
    for (int a = 0; a < 4; a++)
#pragma unroll
        for (int b = 0; b < 4; b++)
#pragma unroll
            for (int c = 0; c < 4; c++) acc[a][b][c] = 0.f;

    int KT = K >> 5;

    auto stage = [&](int kt, int bb){
#pragma unroll
        for (int i = 0; i < 4; i++){
            int q = i*256 + tid;
            int r = q >> 3;
            int c = (q & 7) * 4;
            cp16(&As[bb*128*TSD + r*TSD + c], &A[(size_t)(m0 + r)*K + kt*32 + c]);
            int nr = n0 + r;
            int nc = nr < N ? nr : (N-1);
            cp16z(&Bs[bb*128*TSD + r*TSD + c], &W[(size_t)nc*K + kt*32 + c], nr < N);
        }
        cp_commit();
    };

    stage(0, 0);
    stage(1, 1);

    for (int kt = 0; kt < KT; kt++){
        if (kt < KT-1) cp_wait1(); else cp_wait0();
        __syncthreads();
        int bb = kt & 1;
        const float* Ab = As + bb*128*TSD + wm*64*TSD;
        const float* Bb = Bs + bb*128*TSD + wn*32*TSD;
#pragma unroll
        for (int kk = 0; kk < 4; kk++){
            int kc = kk*8;
            unsigned af[4][4], bf[4][2];
#pragma unroll
            for (int mt = 0; mt < 4; mt++){
                const float* p = Ab + mt*16*TSD + kc;
                af[mt][0] = __float_as_uint(p[g*TSD + tg]);
                af[mt][1] = __float_as_uint(p[(g+8)*TSD + tg]);
                af[mt][2] = __float_as_uint(p[g*TSD + tg + 4]);
                af[mt][3] = __float_as_uint(p[(g+8)*TSD + tg + 4]);
            }
#pragma unroll
            for (int nt = 0; nt < 4; nt++){
                const float* p = Bb + nt*8*TSD + kc;
                bf[nt][0] = __float_as_uint(p[g*TSD + tg]);
                bf[nt][1] = __float_as_uint(p[g*TSD + tg + 4]);
            }
#pragma unroll
            for (int mt = 0; mt < 4; mt++)
#pragma unroll
                for (int nt = 0; nt < 4; nt++)
                    mma8(acc[mt][nt], af[mt], bf[nt]);
        }
        __syncthreads();
        if (kt + 2 < KT) stage(kt+2, bb);
    }

#pragma unroll
    for (int mt = 0; mt < 4; mt++){
        int row = m0 + wm*64 + mt*16 + g;
#pragma unroll
        for (int nt = 0; nt < 4; nt++){
            int col = n0 + wn*32 + nt*8 + 2*tg;
            if (col < N){
                float b0 = bias[col], b1 = bias[col+1];
                float v0 = acc[mt][nt][0] + b0;
                float v1 = acc[mt][nt][1] + b1;
                float v2 = acc[mt][nt][2] + b0;
                float v3 = acc[mt][nt][3] + b1;
                if (relu){
                    v0 = fmaxf(v0, 0.f); v1 = fmaxf(v1, 0.f);
                    v2 = fmaxf(v2, 0.f); v3 = fmaxf(v3, 0.f);
                }
                *(float2*)&C[(size_t)row*N + col]     = make_float2(v0, v1);
                *(float2*)&C[(size_t)(row+8)*N + col] = make_float2(v2, v3);
            }
        }
    }
}

// ------------------- persistent bidirectional LSTM layer -------------------
// 64 blocks x 256 threads. dir = bx>>5, ns = bx&31. Block owns gate cols [ns*64, +64)
// (gate-interleaved) of its direction = hidden units [ns*16, +16).
#define WHS 516
#define HSS 68
__global__ __launch_bounds__(256) void lstm_layer(
    const float* __restrict__ pre,
    const float* __restrict__ whhF, const float* __restrict__ whhB,
    float* __restrict__ out, int gen0)
{
    extern __shared__ float sm[];
    float* whh_s = sm;                       // [64][516]
    float* h_s0  = whh_s + 64*WHS;           // [64][68]
    float* h_s1  = h_s0 + 64*HSS;            // [64][68]
    float* G_s   = h_s1 + 64*HSS;            // [64][68]
    float* c_s   = G_s + 64*HSS;             // [64][16]

    int tid = threadIdx.x;
    int warp = tid >> 5, lane = tid & 31;
    int wm = warp >> 2, wn = warp & 3;       // 2 x 4 warps, warp tile 32(m) x 16(n)
    int g = lane >> 2, tg = lane & 3;
    int dir = blockIdx.x >> 5;
    int ns  = blockIdx.x & 31;
    int n0  = ns*64;
    int j0  = ns*16;
    const float* whh = dir ? whhB : whhF;

    // persistent Whh slice (raw fp32 bits used as tf32)
    for (int q = tid; q < 64*128; q += 256){
        int r = q >> 7;
        int c = (q & 127)*4;
        *(float4*)&whh_s[r*WHS + c] = *(const float4*)&whh[(n0 + r)*512 + c];
    }
    for (int q = tid; q < 64*16; q += 256) c_s[q] = 0.f;
    __syncthreads();

    // gate-update thread mapping
    int ub = tid >> 2;          // batch 0..63
    int uu = (tid & 3)*4;       // first of 4 units

    for (int s = 0; s < SEQ; s++){
        int t  = dir ? (SEQ-1 - s) : s;
        int rp = s & 1;
        int wp = rp ^ 1;

        float acc[2][2][4];
#pragma unroll
        for (int a = 0; a < 2; a++)
#pragma unroll
            for (int b = 0; b < 2; b++)
#pragma unroll
                for (int c = 0; c < 4; c++) acc[a][b][c] = 0.f;

        if (s > 0){
            const float* hsrc = d_hbuf + (rp*2 + dir)*BATCH*HID;
            float* hb[2] = { h_s0, h_s1 };

            // prefetch chunks 0,1
#pragma unroll
            for (int pc = 0; pc < 2; pc++){
#pragma unroll
                for (int i = 0; i < 4; i++){
                    int q = i*256 + tid;
                    int r = q >> 4;
                    int c = (q & 15)*4;
                    cp16(&hb[pc][r*HSS + c], &hsrc[r*HID + pc*64 + c]);
                }
                cp_commit();
            }

            for (int kc8 = 0; kc8 < 8; kc8++){
                if (kc8 < 7) cp_wait1(); else cp_wait0();
                __syncthreads();
                const float* Aw = hb[kc8 & 1] + wm*32*HSS;
                int kc = kc8*64;
#pragma unroll
                for (int k8 = 0; k8 < 8; k8++){
                    int kcol = k8*8;
                    unsigned af[2][4], bf[2][2];
#pragma unroll
                    for (int mt = 0; mt < 2; mt++){
                        const float* p = Aw + mt*16*HSS + kcol;
                        af[mt][0] = __float_as_uint(p[g*HSS + tg]);
                        af[mt][1] = __float_as_uint(p[(g+8)*HSS + tg]);
                        af[mt][2] = __float_as_uint(p[g*HSS + tg + 4]);
                        af[mt][3] = __float_as_uint(p[(g+8)*HSS + tg + 4]);
                    }
#pragma unroll
                    for (int nt = 0; nt < 2; nt++){
                        const float* p = whh_s + (wn*16 + nt*8)*WHS + kc + kcol;
                        bf[nt][0] = __float_as_uint(p[g*WHS + tg]);
                        bf[nt][1] = __float_as_uint(p[g*WHS + tg + 4]);
                    }
#pragma unroll
                    for (int mt = 0; mt < 2; mt++)
#pragma unroll
                        for (int nt = 0; nt < 2; nt++)
                            mma8(acc[mt][nt], af[mt], bf[nt]);
                }
                __syncthreads();
                if (kc8 + 2 < 8){
                    int pc = kc8 + 2;
#pragma unroll
                    for (int i = 0; i < 4; i++){
                        int q = i*256 + tid;
                        int r = q >> 4;
                        int c = (q & 15)*4;
                        cp16(&hb[pc & 1][r*HSS + c], &hsrc[r*HID + pc*64 + c]);
                    }
                    cp_commit();
                }
            }
        }

        // dump accumulators
#pragma unroll
        for (int mt = 0; mt < 2; mt++){
            int rr = wm*32 + mt*16 + g;
#pragma unroll
            for (int nt = 0; nt < 2; nt++){
                int cc = wn*16 + nt*8 + 2*tg;
                G_s[rr*HSS + cc]        = acc[mt][nt][0];
                G_s[rr*HSS + cc + 1]    = acc[mt][nt][1];
                G_s[(rr+8)*HSS + cc]    = acc[mt][nt][2];
                G_s[(rr+8)*HSS + cc+1]  = acc[mt][nt][3];
            }
        }
        __syncthreads();

        // gate update: thread -> batch ub, units uu..uu+3
        {
            float* hdst = d_hbuf + (wp*2 + dir)*BATCH*HID;
            const float* prow = pre + (size_t)(ub*SEQ + t)*4096 + dir*2048 + n0;
            float hv4[4];
#pragma unroll
            for (int k = 0; k < 4; k++){
                int u = uu + k;
                float4 Gv = *(float4*)&G_s[ub*HSS + 4*u];
                float4 Pv = *(const float4*)&prow[4*u];
                float iv = Gv.x + Pv.x;
                float fv = Gv.y + Pv.y;
                float gv = Gv.z + Pv.z;
                float ov = Gv.w + Pv.w;
                float co = c_s[ub*16 + u];
                float si = 1.f/(1.f + __expf(-iv));
                float sf = 1.f/(1.f + __expf(-fv));
                float so = 1.f/(1.f + __expf(-ov));
                float cn = sf*co + si*tanhf(gv);
                hv4[k] = so*tanhf(cn);
                c_s[ub*16 + u] = cn;
            }
            *(float4*)&hdst[ub*HID + j0 + uu] = *(float4*)hv4;
            *(float4*)&out[(size_t)(ub*SEQ + t)*H2 + dir*HID + j0 + uu] = *(float4*)hv4;
        }

        // per-direction distributed barrier
        __threadfence();
        __syncthreads();
        int target = gen0 + s + 1;
        if (tid == 0) d_slot[dir][ns] = target;
        if (ns == 0){
            if (tid < 32){
                while (d_slot[dir][tid] < target) { }
            }
            __syncthreads();
            if (tid == 0){
                __threadfence();
                d_genv[dir] = target;
            }
        }
        if (tid == 0){
            while (d_genv[dir] < target) { }
        }
        __syncthreads();
    }
}

// ------------------- CRF: one block per batch -------------------
__global__ void crf_kernel(const float* __restrict__ em, const int* __restrict__ tags,
                           const float* __restrict__ start, const float* __restrict__ endv,
                           const float* __restrict__ trans, float* __restrict__ v)
{
    __shared__ float tr[NTAG*49];
    __shared__ float al[2][NTAG];
    __shared__ float red[64];
    __shared__ float num_s;
    int b = blockIdx.x;
    int tid = threadIdx.x;
    const int* tg = tags + b*SEQ;
    const float* eb = em + b*SEQ*NTAG;

    for (int q = tid; q < NTAG*NTAG; q += 64){
        int i = q / NTAG, j = q - i*NTAG;
        tr[i*49 + j] = trans[q];
    }
    float part = 0.f;
    for (int t = tid; t < SEQ; t += 64){
        int tt = tg[t];
        part += eb[t*NTAG + tt];
        if (t < SEQ-1) part += trans[tt*NTAG + tg[t+1]];
    }
    red[tid] = part;
    if (tid < NTAG) al[0][tid] = start[tid] + eb[tid];
    __syncthreads();
    if (tid == 0){
        float s = 0.f;
        for (int i = 0; i < 64; i++) s += red[i];
        num_s = s + start[tg[0]] + endv[tg[SEQ-1]];
    }
    __syncthreads();

    for (int t = 1; t < SEQ; t++){
        int cur = t & 1, prv = cur ^ 1;
        float na = 0.f;
        if (tid < NTAG){
            float m = -1e30f;
            for (int i = 0; i < NTAG; i++) m = fmaxf(m, al[prv][i] + tr[i*49 + tid]);
            float ssum = 0.f;
            for (int i = 0; i < NTAG; i++) ssum += __expf(al[prv][i] + tr[i*49 + tid] - m);
            na = m + logf(ssum) + eb[t*NTAG + tid];
        }
        __syncthreads();
        if (tid < NTAG) al[cur][tid] = na;
        __syncthreads();
    }

    if (tid == 0){
        const float* a = al[(SEQ-1) & 1];
        float m = -1e30f;
        for (int j = 0; j < NTAG; j++) m = fmaxf(m, a[j] + endv[j]);
        float s = 0.f;
        for (int j = 0; j < NTAG; j++) s += __expf(a[j] + endv[j] - m);
        v[b] = num_s - (m + logf(s));
    }
}

__global__ void final_reduce(const float* __restrict__ v, float* __restrict__ out){
    __shared__ float s[64];
    s[threadIdx.x] = v[threadIdx.x];
    __syncthreads();
    if (threadIdx.x == 0){
        float a = 0.f;
        for (int i = 0; i < 64; i++) a += s[i];
        out[0] = -(a / 64.f);
    }
}

// ------------------- launch -------------------
extern "C" void kernel_launch(void* const* d_in, const int* in_sizes, int n_in,
                              void* d_out, int out_size)
{
    const float* inputs = (const float*)d_in[0];
    const int*   tags   = (const int*)d_in[1];
    const float *Wih0f=(const float*)d_in[2],  *Whh0f=(const float*)d_in[3],
                *bih0f=(const float*)d_in[4],  *bhh0f=(const float*)d_in[5];
    const float *Wih0b=(const float*)d_in[6],  *Whh0b=(const float*)d_in[7],
                *bih0b=(const float*)d_in[8],  *bhh0b=(const float*)d_in[9];
    const float *Wih1f=(const float*)d_in[10], *Whh1f=(const float*)d_in[11],
                *bih1f=(const float*)d_in[12], *bhh1f=(const float*)d_in[13];
    const float *Wih1b=(const float*)d_in[14], *Whh1b=(const float*)d_in[15],
                *bih1b=(const float*)d_in[16], *bhh1b=(const float*)d_in[17];
    const float *gamma=(const float*)d_in[18], *beta=(const float*)d_in[19],
                *mean=(const float*)d_in[20],  *var=(const float*)d_in[21];
    const float *fc1w=(const float*)d_in[22], *fc1b=(const float*)d_in[23];
    const float *fc2w=(const float*)d_in[24], *fc2b=(const float*)d_in[25];
    const float *fc3w=(const float*)d_in[26], *fc3b=(const float*)d_in[27];
    const float *crfS=(const float*)d_in[28], *crfE=(const float*)d_in[29],
                *crfT=(const float*)d_in[30];

    float *pW0m,*pW1m,*pWh0f,*pWh0b,*pWh1f,*pWh1b,*pB0m,*pB1m;
    float *pFc1w,*pFc1b,*pPre,*pX1,*pX2,*pF1,*pF2,*pEm,*pV;
    cudaGetSymbolAddress((void**)&pW0m, d_W0m);
    cudaGetSymbolAddress((void**)&pW1m, d_W1m);
    cudaGetSymbolAddress((void**)&pWh0f, d_Wh0f);
    cudaGetSymbolAddress((void**)&pWh0b, d_Wh0b);
    cudaGetSymbolAddress((void**)&pWh1f, d_Wh1f);
    cudaGetSymbolAddress((void**)&pWh1b, d_Wh1b);
    cudaGetSymbolAddress((void**)&pB0m, d_b0m);
    cudaGetSymbolAddress((void**)&pB1m, d_b1m);
    cudaGetSymbolAddress((void**)&pFc1w, d_fc1wP);
    cudaGetSymbolAddress((void**)&pFc1b, d_fc1bP);
    cudaGetSymbolAddress((void**)&pPre, d_pre);
    cudaGetSymbolAddress((void**)&pX1, d_x1);
    cudaGetSymbolAddress((void**)&pX2, d_x2);
    cudaGetSymbolAddress((void**)&pF1, d_f1);
    cudaGetSymbolAddress((void**)&pF2, d_f2);
    cudaGetSymbolAddress((void**)&pEm, d_em);
    cudaGetSymbolAddress((void**)&pV, d_v);

    const int gemm_smem = 2*2*128*TSD*4;
    const int lstm_smem = (64*WHS + 2*64*HSS + 64*HSS + 64*16)*4;
    cudaFuncSetAttribute(gemm_tf32, cudaFuncAttributeMaxDynamicSharedMemorySize, gemm_smem);
    cudaFuncSetAttribute(lstm_layer, cudaFuncAttributeMaxDynamicSharedMemorySize, lstm_smem);

    // 0: prep_all
    prep_all<<<2048,256>>>(Wih0f, Wih0b, Whh0f, Whh0b, Wih1f, Wih1b, Whh1f, Whh1b,
                           bih0f, bhh0f, bih0b, bhh0b, bih1f, bhh1f, bih1b, bhh1b);
    // 1: prep_fc
    prep_fc<<<512,256>>>(fc1w, fc1b, gamma, beta, mean, var);
    // 2: layer-0 input projection (merged fwd+bwd, N=4096)
    gemm_tf32<<<dim3(32,128),256,gemm_smem>>>(inputs, pW0m, pB0m, pPre, MROWS, 4096, 256, 0);
    // 3: layer-0 recurrence
    lstm_layer<<<64,256,lstm_smem>>>(pPre, pWh0f, pWh0b, pX1, 0);
    // 4: layer-1 input projection
    gemm_tf32<<<dim3(32,128),256,gemm_smem>>>(pX1, pW1m, pB1m, pPre, MROWS, 4096, 1024, 0);
    // 5: layer-1 recurrence (ncu -s 5 profiles this)
    lstm_layer<<<64,256,lstm_smem>>>(pPre, pWh1f, pWh1b, pX2, 256);
    // 6-8: head (BN folded into fc1)
    gemm_tf32<<<dim3(4,128),256,gemm_smem>>>(pX2, pFc1w, pFc1b, pF1, MROWS, 512, 1024, 1);
    gemm_tf32<<<dim3(2,128),256,gemm_smem>>>(pF1, fc2w, fc2b, pF2, MROWS, 256, 512, 1);
    gemm_tf32<<<dim3(1,128),256,gemm_smem>>>(pF2, fc3w, fc3b, pEm, MROWS, NTAG, 256, 0);
    // 9-10: CRF + reduce
    crf_kernel<<<64,64>>>(pEm, tags, crfS, crfE, crfT, pV);
    final_reduce<<<1,64>>>(pV, (float*)d_out);
}

// round 4
// speedup vs baseline: 2.1082x; 1.0521x over previous
#include <cuda_runtime.h>
#include <cuda_bf16.h>
#include <cstdint>

#define BATCH 64
#define SEQ   256
#define HID   512
#define NTAG  48
#define MROWS (BATCH*SEQ)     // 16384
#define G4    2048
#define H2    1024

typedef __nv_bfloat16 bf16;
typedef __nv_bfloat162 bf162;

// ------------------- static device scratch -------------------
__device__ bf16  d_inb[16384*256];
__device__ bf16  d_W0m[4096*256];
__device__ bf16  d_W1m[4096*1024];
__device__ float d_Wh0f[2048*512];
__device__ float d_Wh0b[2048*512];
__device__ float d_Wh1f[2048*512];
__device__ float d_Wh1b[2048*512];
__device__ float d_b0m[4096];
__device__ float d_b1m[4096];
__device__ bf16  d_fc1wP[512*1024];
__device__ float d_fc1bP[512];
__device__ bf16  d_fc2wB[256*512];
__device__ bf16  d_fc3wB[48*256];
__device__ float d_pre[16384*4096];
__device__ bf16  d_x1[16384*1024];
__device__ bf16  d_x2[16384*1024];
__device__ bf16  d_f1[16384*512];
__device__ bf16  d_f2[16384*256];
__device__ float d_em[16384*48];
__device__ float d_hbuf[2*2*BATCH*HID];
__device__ float d_v[64];
__device__ volatile int d_slot[2][32];
__device__ volatile int d_genv[2];

// ------------------- helpers -------------------
__device__ __forceinline__ void mma8(float* c, const unsigned* a, const unsigned* b){
    asm volatile(
        "mma.sync.aligned.m16n8k8.row.col.f32.tf32.tf32.f32 "
        "{%0,%1,%2,%3}, {%4,%5,%6,%7}, {%8,%9}, {%0,%1,%2,%3};\n"
        : "+f"(c[0]), "+f"(c[1]), "+f"(c[2]), "+f"(c[3])
        : "r"(a[0]), "r"(a[1]), "r"(a[2]), "r"(a[3]),
          "r"(b[0]), "r"(b[1]));
}

__device__ __forceinline__ void mma16(float* c, const unsigned* a, const unsigned* b){
    asm volatile(
        "mma.sync.aligned.m16n8k16.row.col.f32.bf16.bf16.f32 "
        "{%0,%1,%2,%3}, {%4,%5,%6,%7}, {%8,%9}, {%0,%1,%2,%3};\n"
        : "+f"(c[0]), "+f"(c[1]), "+f"(c[2]), "+f"(c[3])
        : "r"(a[0]), "r"(a[1]), "r"(a[2]), "r"(a[3]),
          "r"(b[0]), "r"(b[1]));
}

__device__ __forceinline__ void cp16(void* smem, const void* gmem){
    unsigned sa = (unsigned)__cvta_generic_to_shared(smem);
    asm volatile("cp.async.cg.shared.global [%0], [%1], 16;" :: "r"(sa), "l"(gmem));
}
__device__ __forceinline__ void cp16z(void* smem, const void* gmem, int pred){
    unsigned sa = (unsigned)__cvta_generic_to_shared(smem);
    int bytes = pred ? 16 : 0;
    asm volatile("cp.async.cg.shared.global [%0], [%1], 16, %2;" :: "r"(sa), "l"(gmem), "r"(bytes));
}
__device__ __forceinline__ void cp_commit(){ asm volatile("cp.async.commit_group;"); }
__device__ __forceinline__ void cp_wait0(){ asm volatile("cp.async.wait_group 0;"); }
__device__ __forceinline__ void cp_wait1(){ asm volatile("cp.async.wait_group 1;"); }

// ------------------- prep -------------------
__global__ void prep_all(
    const float* __restrict__ inputs,
    const float* __restrict__ Wih0f, const float* __restrict__ Wih0b,
    const float* __restrict__ Whh0f, const float* __restrict__ Whh0b,
    const float* __restrict__ Wih1f, const float* __restrict__ Wih1b,
    const float* __restrict__ Whh1f, const float* __restrict__ Whh1b,
    const float* __restrict__ bih0f, const float* __restrict__ bhh0f,
    const float* __restrict__ bih0b, const float* __restrict__ bhh0b,
    const float* __restrict__ bih1f, const float* __restrict__ bhh1f,
    const float* __restrict__ bih1b, const float* __restrict__ bhh1b,
    const float* __restrict__ fc2w, const float* __restrict__ fc3w)
{
    const int NIN = 16384*256;
    const int NW0 = 4096*256;
    const int NW1 = 4096*1024;
    const int NWH = 2048*512;
    const int e0 = NIN;                 // inb
    const int e1 = e0 + NW0;            // W0m
    const int e2 = e1 + NW1;            // W1m
    const int e3 = e2 + 4*NWH;          // Wh x4
    const int e4 = e3 + 4096;           // b0m
    const int e5 = e4 + 4096;           // b1m
    const int e6 = e5 + 256*512;        // fc2
    const int e7 = e6 + 48*256;         // fc3
    const int total = e7 + 66;          // ctrl
    int stride = gridDim.x * blockDim.x;
    for (int i = blockIdx.x*blockDim.x + threadIdx.x; i < total; i += stride){
        if (i < e0){
            d_inb[i] = __float2bfloat16_rn(inputs[i]);
        } else if (i < e1){
            int j = i - e0;
            int np = j >> 8, k = j & 255;
            int np2 = np & 2047;
            int sr = (np2 & 3)*512 + (np2 >> 2);
            const float* src = (np < 2048) ? Wih0f : Wih0b;
            d_W0m[j] = __float2bfloat16_rn(src[sr*256 + k]);
        } else if (i < e2){
            int j = i - e1;
            int np = j >> 10, k = j & 1023;
            int np2 = np & 2047;
            int sr = (np2 & 3)*512 + (np2 >> 2);
            const float* src = (np < 2048) ? Wih1f : Wih1b;
            d_W1m[j] = __float2bfloat16_rn(src[sr*1024 + k]);
        } else if (i < e3){
            int j = i - e2;
            int arr = j / NWH;
            int jj = j - arr*NWH;
            int np = jj >> 9, k = jj & 511;
            int sr = (np & 3)*512 + (np >> 2);
            const float* src = (arr==0)?Whh0f:(arr==1)?Whh0b:(arr==2)?Whh1f:Whh1b;
            float* dst = (arr==0)?d_Wh0f:(arr==1)?d_Wh0b:(arr==2)?d_Wh1f:d_Wh1b;
            dst[jj] = src[sr*512 + k];
        } else if (i < e4){
            int np = i - e3;
            int np2 = np & 2047;
            int sr = (np2 & 3)*512 + (np2 >> 2);
            d_b0m[np] = (np < 2048) ? (bih0f[sr] + bhh0f[sr]) : (bih0b[sr] + bhh0b[sr]);
        } else if (i < e5){
            int np = i - e4;
            int np2 = np & 2047;
            int sr = (np2 & 3)*512 + (np2 >> 2);
            d_b1m[np] = (np < 2048) ? (bih1f[sr] + bhh1f[sr]) : (bih1b[sr] + bhh1b[sr]);
        } else if (i < e6){
            int j = i - e5;
            d_fc2wB[j] = __float2bfloat16_rn(fc2w[j]);
        } else if (i < e7){
            int j = i - e6;
            d_fc3wB[j] = __float2bfloat16_rn(fc3w[j]);
        } else {
            int j = i - e7;
            if (j < 64) ((volatile int*)d_slot)[j] = 0;
            else d_genv[j - 64] = 0;
        }
    }
}

// fold BN into fc1: W' = fc1_w * s[c] (bf16), b' = fc1_b + fc1_w @ t
__global__ void prep_fc(const float* __restrict__ fc1w, const float* __restrict__ fc1b,
                        const float* __restrict__ gamma, const float* __restrict__ beta,
                        const float* __restrict__ mean, const float* __restrict__ var)
{
    __shared__ float red[256];
    int r = blockIdx.x;
    int tid = threadIdx.x;
    float part = 0.f;
    for (int c = tid; c < 1024; c += 256){
        float sc = gamma[c] * rsqrtf(var[c] + 1e-5f);
        float tc = beta[c] - mean[c]*sc;
        float w = fc1w[r*1024 + c];
        d_fc1wP[r*1024 + c] = __float2bfloat16_rn(w * sc);
        part += w * tc;
    }
    red[tid] = part;
    __syncthreads();
    for (int off = 128; off > 0; off >>= 1){
        if (tid < off) red[tid] += red[tid + off];
        __syncthreads();
    }
    if (tid == 0) d_fc1bP[r] = fc1b[r] + red[0];
}

__global__ void ctrl_reset(){
    int i = threadIdx.x;
    if (i < 64) ((volatile int*)d_slot)[i] = 0;
    else if (i < 66) d_genv[i-64] = 0;
}

// ------------------- bf16 GEMM: C = A(MxK) @ W(NxK)^T + bias -------------------
// 128x128x32 tiles, 256 thr, 8 warps (2x4), warp tile 64x32. Conflict-free stride 40.
#define BRS 40
__global__ __launch_bounds__(256) void gemm_bf16(
    const bf16* __restrict__ A, const bf16* __restrict__ W,
    const float* __restrict__ bias, void* __restrict__ Cv,
    int M, int N, int K, int relu, int outBf)
{
    extern __shared__ bf16 smb[];
    bf16* As = smb;                 // [2][128][BRS]
    bf16* Bs = smb + 2*128*BRS;     // [2][128][BRS]
    int tid  = threadIdx.x;
    int warp = tid >> 5, lane = tid & 31;
    int wm = warp >> 2, wn = warp & 3;
    int g = lane >> 2, tg = lane & 3;
    int m0 = blockIdx.y*128, n0 = blockIdx.x*128;

    float acc[4][4][4];
#pragma unroll
    for (int a = 0; a < 4; a++)
#pragma unroll
        for (int b = 0; b < 4; b++)
#pragma unroll
            for (int c = 0; c < 4; c++) acc[a][b][c] = 0.f;

    int KT = K >> 5;

    auto stage = [&](int kt, int bb){
        const bf16* Ag = A + (size_t)m0*K + kt*32;
#pragma unroll
        for (int i = 0; i < 2; i++){
            int q = i*256 + tid;
            int r = q >> 2;
            int c = (q & 3) * 8;
            cp16(&As[bb*128*BRS + r*BRS + c], Ag + (size_t)r*K + c);
        }
        const bf16* Wg = W + kt*32;
#pragma unroll
        for (int i = 0; i < 2; i++){
            int q = i*256 + tid;
            int r = q >> 2;
            int c = (q & 3) * 8;
            int nr = n0 + r;
            int nc = nr < N ? nr : 0;
            cp16z(&Bs[bb*128*BRS + r*BRS + c], Wg + (size_t)nc*K + c, nr < N);
        }
        cp_commit();
    };

    stage(0, 0);
    if (KT > 1) stage(1, 1);

    for (int kt = 0; kt < KT; kt++){
        if (kt < KT-1) cp_wait1(); else cp_wait0();
        __syncthreads();
        int bb = kt & 1;
        const bf16* Ab = As + bb*128*BRS + (wm*64)*BRS;
        const bf16* Bb = Bs + bb*128*BRS + (wn*32)*BRS;
#pragma unroll
        for (int kk = 0; kk < 2; kk++){
            int kc = kk*16 + tg*2;
            unsigned af[4][4], bf[4][2];
#pragma unroll
            for (int mt = 0; mt < 4; mt++){
                const bf16* p = Ab + (mt*16 + g)*BRS + kc;
                af[mt][0] = *(const unsigned*)p;
                af[mt][1] = *(const unsigned*)(p + 8*BRS);
                af[mt][2] = *(const unsigned*)(p + 8);
                af[mt][3] = *(const unsigned*)(p + 8*BRS + 8);
            }
#pragma unroll
            for (int nt = 0; nt < 4; nt++){
                const bf16* p = Bb + (nt*8 + g)*BRS + kc;
                bf[nt][0] = *(const unsigned*)p;
                bf[nt][1] = *(const unsigned*)(p + 8);
            }
#pragma unroll
            for (int mt = 0; mt < 4; mt++)
#pragma unroll
                for (int nt = 0; nt < 4; nt++)
                    mma16(acc[mt][nt], af[mt], bf[nt]);
        }
        __syncthreads();
        if (kt + 2 < KT) stage(kt+2, bb);
    }

#pragma unroll
    for (int mt = 0; mt < 4; mt++){
        int row = m0 + wm*64 + mt*16 + g;
#pragma unroll
        for (int nt = 0; nt < 4; nt++){
            int col = n0 + wn*32 + nt*8 + 2*tg;
            if (col < N){
                float b0 = bias[col], b1 = bias[col+1];
                float v0 = acc[mt][nt][0] + b0;
                float v1 = acc[mt][nt][1] + b1;
                float v2 = acc[mt][nt][2] + b0;
                float v3 = acc[mt][nt][3] + b1;
                if (relu){
                    v0 = fmaxf(v0, 0.f); v1 = fmaxf(v1, 0.f);
                    v2 = fmaxf(v2, 0.f); v3 = fmaxf(v3, 0.f);
                }
                if (outBf){
                    bf16* C16 = (bf16*)Cv;
                    *(bf162*)&C16[(size_t)row*N + col]     = __floats2bfloat162_rn(v0, v1);
                    *(bf162*)&C16[(size_t)(row+8)*N + col] = __floats2bfloat162_rn(v2, v3);
                } else {
                    float* C = (float*)Cv;
                    *(float2*)&C[(size_t)row*N + col]     = make_float2(v0, v1);
                    *(float2*)&C[(size_t)(row+8)*N + col] = make_float2(v2, v3);
                }
            }
        }
    }
}

// ------------------- persistent bidirectional LSTM layer (tf32 recurrence) -------------------
#define WHS 516
#define HSS 68
__global__ __launch_bounds__(256) void lstm_layer(
    const float* __restrict__ pre,
    const float* __restrict__ whhF, const float* __restrict__ whhB,
    bf16* __restrict__ out, int gen0)
{
    extern __shared__ float sm[];
    float* whh_s = sm;                       // [64][516]
    float* h_s0  = whh_s + 64*WHS;           // [64][68]
    float* h_s1  = h_s0 + 64*HSS;
    float* G_s   = h_s1 + 64*HSS;
    float* c_s   = G_s + 64*HSS;             // [64][16]

    int tid = threadIdx.x;
    int warp = tid >> 5, lane = tid & 31;
    int wm = warp >> 2, wn = warp & 3;
    int g = lane >> 2, tg = lane & 3;
    int dir = blockIdx.x >> 5;
    int ns  = blockIdx.x & 31;
    int n0  = ns*64;
    int j0  = ns*16;
    const float* whh = dir ? whhB : whhF;

    for (int q = tid; q < 64*128; q += 256){
        int r = q >> 7;
        int c = (q & 127)*4;
        *(float4*)&whh_s[r*WHS + c] = *(const float4*)&whh[(n0 + r)*512 + c];
    }
    for (int q = tid; q < 64*16; q += 256) c_s[q] = 0.f;
    __syncthreads();

    int ub = tid >> 2;
    int uu = (tid & 3)*4;

    for (int s = 0; s < SEQ; s++){
        int t  = dir ? (SEQ-1 - s) : s;
        int rp = s & 1;
        int wp = rp ^ 1;

        float acc[2][2][4];
#pragma unroll
        for (int a = 0; a < 2; a++)
#pragma unroll
            for (int b = 0; b < 2; b++)
#pragma unroll
                for (int c = 0; c < 4; c++) acc[a][b][c] = 0.f;

        if (s > 0){
            const float* hsrc = d_hbuf + (rp*2 + dir)*BATCH*HID;
            float* hb[2] = { h_s0, h_s1 };

#pragma unroll
            for (int pc = 0; pc < 2; pc++){
#pragma unroll
                for (int i = 0; i < 4; i++){
                    int q = i*256 + tid;
                    int r = q >> 4;
                    int c = (q & 15)*4;
                    cp16(&hb[pc][r*HSS + c], &hsrc[r*HID + pc*64 + c]);
                }
                cp_commit();
            }

            for (int kc8 = 0; kc8 < 8; kc8++){
                if (kc8 < 7) cp_wait1(); else cp_wait0();
                __syncthreads();
                const float* Aw = hb[kc8 & 1] + wm*32*HSS;
                int kc = kc8*64;
#pragma unroll
                for (int k8 = 0; k8 < 8; k8++){
                    int kcol = k8*8;
                    unsigned af[2][4], bf[2][2];
#pragma unroll
                    for (int mt = 0; mt < 2; mt++){
                        const float* p = Aw + mt*16*HSS + kcol;
                        af[mt][0] = __float_as_uint(p[g*HSS + tg]);
                        af[mt][1] = __float_as_uint(p[(g+8)*HSS + tg]);
                        af[mt][2] = __float_as_uint(p[g*HSS + tg + 4]);
                        af[mt][3] = __float_as_uint(p[(g+8)*HSS + tg + 4]);
                    }
#pragma unroll
                    for (int nt = 0; nt < 2; nt++){
                        const float* p = whh_s + (wn*16 + nt*8)*WHS + kc + kcol;
                        bf[nt][0] = __float_as_uint(p[g*WHS + tg]);
                        bf[nt][1] = __float_as_uint(p[g*WHS + tg + 4]);
                    }
#pragma unroll
                    for (int mt = 0; mt < 2; mt++)
#pragma unroll
                        for (int nt = 0; nt < 2; nt++)
                            mma8(acc[mt][nt], af[mt], bf[nt]);
                }
                __syncthreads();
                if (kc8 + 2 < 8){
                    int pc = kc8 + 2;
#pragma unroll
                    for (int i = 0; i < 4; i++){
                        int q = i*256 + tid;
                        int r = q >> 4;
                        int c = (q & 15)*4;
                        cp16(&hb[pc & 1][r*HSS + c], &hsrc[r*HID + pc*64 + c]);
                    }
                    cp_commit();
                }
            }
        }

#pragma unroll
        for (int mt = 0; mt < 2; mt++){
            int rr = wm*32 + mt*16 + g;
#pragma unroll
            for (int nt = 0; nt < 2; nt++){
                int cc = wn*16 + nt*8 + 2*tg;
                G_s[rr*HSS + cc]        = acc[mt][nt][0];
                G_s[rr*HSS + cc + 1]    = acc[mt][nt][1];
                G_s[(rr+8)*HSS + cc]    = acc[mt][nt][2];
                G_s[(rr+8)*HSS + cc+1]  = acc[mt][nt][3];
            }
        }
        __syncthreads();

        {
            float* hdst = d_hbuf + (wp*2 + dir)*BATCH*HID;
            const float* prow = pre + (size_t)(ub*SEQ + t)*4096 + dir*2048 + n0;
            float hv4[4];
#pragma unroll
            for (int k = 0; k < 4; k++){
                int u = uu + k;
                float4 Gv = *(float4*)&G_s[ub*HSS + 4*u];
                float4 Pv = *(const float4*)&prow[4*u];
                float iv = Gv.x + Pv.x;
                float fv = Gv.y + Pv.y;
                float gv = Gv.z + Pv.z;
                float ov = Gv.w + Pv.w;
                float co = c_s[ub*16 + u];
                float si = 1.f/(1.f + __expf(-iv));
                float sf = 1.f/(1.f + __expf(-fv));
                float so = 1.f/(1.f + __expf(-ov));
                float cn = sf*co + si*tanhf(gv);
                hv4[k] = so*tanhf(cn);
                c_s[ub*16 + u] = cn;
            }
            *(float4*)&hdst[ub*HID + j0 + uu] = *(float4*)hv4;
            bf162 p0 = __floats2bfloat162_rn(hv4[0], hv4[1]);
            bf162 p1 = __floats2bfloat162_rn(hv4[2], hv4[3]);
            uint2 pk = make_uint2(*(unsigned*)&p0, *(unsigned*)&p1);
            *(uint2*)&out[(size_t)(ub*SEQ + t)*H2 + dir*HID + j0 + uu] = pk;
        }

        __threadfence();
        __syncthreads();
        int target = gen0 + s + 1;
        if (tid == 0) d_slot[dir][ns] = target;
        if (ns == 0){
            if (tid < 32){
                while (d_slot[dir][tid] < target) { }
            }
            __syncthreads();
            if (tid == 0){
                __threadfence();
                d_genv[dir] = target;
            }
        }
        if (tid == 0){
            while (d_genv[dir] < target) { }
        }
        __syncthreads();
    }
}

// ------------------- CRF -------------------
__global__ void crf_kernel(const float* __restrict__ em, const int* __restrict__ tags,
                           const float* __restrict__ start, const float* __restrict__ endv,
                           const float* __restrict__ trans, float* __restrict__ v)
{
    __shared__ float tr[NTAG*49];
    __shared__ float al[2][NTAG];
    __shared__ float red[64];
    __shared__ float num_s;
    int b = blockIdx.x;
    int tid = threadIdx.x;
    const int* tg = tags + b*SEQ;
    const float* eb = em + b*SEQ*NTAG;

    for (int q = tid; q < NTAG*NTAG; q += 64){
        int i = q / NTAG, j = q - i*NTAG;
        tr[i*49 + j] = trans[q];
    }
    float part = 0.f;
    for (int t = tid; t < SEQ; t += 64){
        int tt = tg[t];
        part += eb[t*NTAG + tt];
        if (t < SEQ-1) part += trans[tt*NTAG + tg[t+1]];
    }
    red[tid] = part;
    if (tid < NTAG) al[0][tid] = start[tid] + eb[tid];
    __syncthreads();
    if (tid == 0){
        float s = 0.f;
        for (int i = 0; i < 64; i++) s += red[i];
        num_s = s + start[tg[0]] + endv[tg[SEQ-1]];
    }
    __syncthreads();

    for (int t = 1; t < SEQ; t++){
        int cur = t & 1, prv = cur ^ 1;
        float na = 0.f;
        if (tid < NTAG){
            float m = -1e30f;
            for (int i = 0; i < NTAG; i++) m = fmaxf(m, al[prv][i] + tr[i*49 + tid]);
            float ssum = 0.f;
            for (int i = 0; i < NTAG; i++) ssum += __expf(al[prv][i] + tr[i*49 + tid] - m);
            na = m + logf(ssum) + eb[t*NTAG + tid];
        }
        __syncthreads();
        if (tid < NTAG) al[cur][tid] = na;
        __syncthreads();
    }

    if (tid == 0){
        const float* a = al[(SEQ-1) & 1];
        float m = -1e30f;
        for (int j = 0; j < NTAG; j++) m = fmaxf(m, a[j] + endv[j]);
        float s = 0.f;
        for (int j = 0; j < NTAG; j++) s += __expf(a[j] + endv[j] - m);
        v[b] = num_s - (m + logf(s));
    }
}

__global__ void final_reduce(const float* __restrict__ v, float* __restrict__ out){
    __shared__ float s[64];
    s[threadIdx.x] = v[threadIdx.x];
    __syncthreads();
    if (threadIdx.x == 0){
        float a = 0.f;
        for (int i = 0; i < 64; i++) a += s[i];
        out[0] = -(a / 64.f);
    }
}

// ------------------- launch -------------------
extern "C" void kernel_launch(void* const* d_in, const int* in_sizes, int n_in,
                              void* d_out, int out_size)
{
    const float* inputs = (const float*)d_in[0];
    const int*   tags   = (const int*)d_in[1];
    const float *Wih0f=(const float*)d_in[2],  *Whh0f=(const float*)d_in[3],
                *bih0f=(const float*)d_in[4],  *bhh0f=(const float*)d_in[5];
    const float *Wih0b=(const float*)d_in[6],  *Whh0b=(const float*)d_in[7],
                *bih0b=(const float*)d_in[8],  *bhh0b=(const float*)d_in[9];
    const float *Wih1f=(const float*)d_in[10], *Whh1f=(const float*)d_in[11],
                *bih1f=(const float*)d_in[12], *bhh1f=(const float*)d_in[13];
    const float *Wih1b=(const float*)d_in[14], *Whh1b=(const float*)d_in[15],
                *bih1b=(const float*)d_in[16], *bhh1b=(const float*)d_in[17];
    const float *gamma=(const float*)d_in[18], *beta=(const float*)d_in[19],
                *mean=(const float*)d_in[20],  *var=(const float*)d_in[21];
    const float *fc1w=(const float*)d_in[22], *fc1b=(const float*)d_in[23];
    const float *fc2w=(const float*)d_in[24], *fc2b=(const float*)d_in[25];
    const float *fc3w=(const float*)d_in[26], *fc3b=(const float*)d_in[27];
    const float *crfS=(const float*)d_in[28], *crfE=(const float*)d_in[29],
                *crfT=(const float*)d_in[30];

    bf16 *pInb,*pW0m,*pW1m,*pFc1w,*pFc2w,*pFc3w,*pX1,*pX2,*pF1,*pF2;
    float *pWh0f,*pWh0b,*pWh1f,*pWh1b,*pB0m,*pB1m,*pFc1b,*pPre,*pEm,*pV;
    cudaGetSymbolAddress((void**)&pInb, d_inb);
    cudaGetSymbolAddress((void**)&pW0m, d_W0m);
    cudaGetSymbolAddress((void**)&pW1m, d_W1m);
    cudaGetSymbolAddress((void**)&pWh0f, d_Wh0f);
    cudaGetSymbolAddress((void**)&pWh0b, d_Wh0b);
    cudaGetSymbolAddress((void**)&pWh1f, d_Wh1f);
    cudaGetSymbolAddress((void**)&pWh1b, d_Wh1b);
    cudaGetSymbolAddress((void**)&pB0m, d_b0m);
    cudaGetSymbolAddress((void**)&pB1m, d_b1m);
    cudaGetSymbolAddress((void**)&pFc1w, d_fc1wP);
    cudaGetSymbolAddress((void**)&pFc1b, d_fc1bP);
    cudaGetSymbolAddress((void**)&pFc2w, d_fc2wB);
    cudaGetSymbolAddress((void**)&pFc3w, d_fc3wB);
    cudaGetSymbolAddress((void**)&pPre, d_pre);
    cudaGetSymbolAddress((void**)&pX1, d_x1);
    cudaGetSymbolAddress((void**)&pX2, d_x2);
    cudaGetSymbolAddress((void**)&pF1, d_f1);
    cudaGetSymbolAddress((void**)&pF2, d_f2);
    cudaGetSymbolAddress((void**)&pEm, d_em);
    cudaGetSymbolAddress((void**)&pV, d_v);

    const int gemm_smem = 2*2*128*BRS*2;   // bf16
    const int lstm_smem = (64*WHS + 2*64*HSS + 64*HSS + 64*16)*4;
    cudaFuncSetAttribute(gemm_bf16, cudaFuncAttributeMaxDynamicSharedMemorySize, gemm_smem);
    cudaFuncSetAttribute(lstm_layer, cudaFuncAttributeMaxDynamicSharedMemorySize, lstm_smem);

    // 0: prep_all
    prep_all<<<2048,256>>>(inputs, Wih0f, Wih0b, Whh0f, Whh0b, Wih1f, Wih1b, Whh1f, Whh1b,
                           bih0f, bhh0f, bih0b, bhh0b, bih1f, bhh1f, bih1b, bhh1b,
                           fc2w, fc3w);
    // 1: prep_fc
    prep_fc<<<512,256>>>(fc1w, fc1b, gamma, beta, mean, var);
    // 2: layer-0 projection
    gemm_bf16<<<dim3(32,128),256,gemm_smem>>>(pInb, pW0m, pB0m, pPre, MROWS, 4096, 256, 0, 0);
    // 3: layer-0 recurrence
    lstm_layer<<<64,256,lstm_smem>>>(pPre, pWh0f, pWh0b, pX1, 0);
    // 4: ctrl_reset (dummy so ncu -s 5 profiles the big GEMM)
    ctrl_reset<<<1,66>>>();
    // 5: layer-1 projection  <-- ncu profiles this
    gemm_bf16<<<dim3(32,128),256,gemm_smem>>>(pX1, pW1m, pB1m, pPre, MROWS, 4096, 1024, 0, 0);
    // 6: layer-1 recurrence
    lstm_layer<<<64,256,lstm_smem>>>(pPre, pWh1f, pWh1b, pX2, 256);
    // 7-9: head
    gemm_bf16<<<dim3(4,128),256,gemm_smem>>>(pX2, pFc1w, pFc1b, pF1, MROWS, 512, 1024, 1, 1);
    gemm_bf16<<<dim3(2,128),256,gemm_smem>>>(pF1, pFc2w, fc2b, pF2, MROWS, 256, 512, 1, 1);
    gemm_bf16<<<dim3(1,128),256,gemm_smem>>>(pF2, pFc3w, fc3b, pEm, MROWS, NTAG, 256, 0, 0);
    // 10-11: CRF + reduce
    crf_kernel<<<64,64>>>(pEm, tags, crfS, crfE, crfT, pV);
    final_reduce<<<1,64>>>(pV, (float*)d_out);
}

// round 5
// speedup vs baseline: 2.5815x; 1.2245x over previous
#include <cuda_runtime.h>
#include <cuda_bf16.h>
#include <cstdint>

#define BATCH 64
#define SEQ   256
#define HID   512
#define NTAG  48
#define MROWS (BATCH*SEQ)     // 16384
#define G4    2048
#define H2    1024

typedef __nv_bfloat16 bf16;
typedef __nv_bfloat162 bf162;

// ------------------- static device scratch -------------------
__device__ bf16  d_inb[16384*256];
__device__ bf16  d_W0m[4096*256];
__device__ bf16  d_W1m[4096*1024];
__device__ bf16  d_Wh0f[2048*512];
__device__ bf16  d_Wh0b[2048*512];
__device__ bf16  d_Wh1f[2048*512];
__device__ bf16  d_Wh1b[2048*512];
__device__ float d_b0m[4096];
__device__ float d_b1m[4096];
__device__ bf16  d_fc1wP[512*1024];
__device__ float d_fc1bP[512];
__device__ bf16  d_fc2wB[256*512];
__device__ bf16  d_fc3wB[48*256];
__device__ bf16  d_pre[(size_t)16384*4096];
__device__ bf16  d_x1[16384*1024];
__device__ bf16  d_x2[16384*1024];
__device__ bf16  d_f1[16384*512];
__device__ bf16  d_f2[16384*256];
__device__ float d_em[16384*48];
__device__ bf16  d_hbuf[2*2*BATCH*HID];   // [parity][dir][b][j]
__device__ float d_v[64];
__device__ volatile int d_slot[2][32];
__device__ volatile int d_genv[2];

// ------------------- helpers -------------------
__device__ __forceinline__ void mma16(float* c, const unsigned* a, const unsigned* b){
    asm volatile(
        "mma.sync.aligned.m16n8k16.row.col.f32.bf16.bf16.f32 "
        "{%0,%1,%2,%3}, {%4,%5,%6,%7}, {%8,%9}, {%0,%1,%2,%3};\n"
        : "+f"(c[0]), "+f"(c[1]), "+f"(c[2]), "+f"(c[3])
        : "r"(a[0]), "r"(a[1]), "r"(a[2]), "r"(a[3]),
          "r"(b[0]), "r"(b[1]));
}

__device__ __forceinline__ void cp16(void* smem, const void* gmem){
    unsigned sa = (unsigned)__cvta_generic_to_shared(smem);
    asm volatile("cp.async.cg.shared.global [%0], [%1], 16;" :: "r"(sa), "l"(gmem));
}
__device__ __forceinline__ void cp16z(void* smem, const void* gmem, int pred){
    unsigned sa = (unsigned)__cvta_generic_to_shared(smem);
    int bytes = pred ? 16 : 0;
    asm volatile("cp.async.cg.shared.global [%0], [%1], 16, %2;" :: "r"(sa), "l"(gmem), "r"(bytes));
}
__device__ __forceinline__ void cp_commit(){ asm volatile("cp.async.commit_group;"); }
__device__ __forceinline__ void cp_wait0(){ asm volatile("cp.async.wait_group 0;"); }
__device__ __forceinline__ void cp_wait1(){ asm volatile("cp.async.wait_group 1;"); }

// ------------------- prep -------------------
__global__ void prep_all(
    const float* __restrict__ inputs,
    const float* __restrict__ Wih0f, const float* __restrict__ Wih0b,
    const float* __restrict__ Whh0f, const float* __restrict__ Whh0b,
    const float* __restrict__ Wih1f, const float* __restrict__ Wih1b,
    const float* __restrict__ Whh1f, const float* __restrict__ Whh1b,
    const float* __restrict__ bih0f, const float* __restrict__ bhh0f,
    const float* __restrict__ bih0b, const float* __restrict__ bhh0b,
    const float* __restrict__ bih1f, const float* __restrict__ bhh1f,
    const float* __restrict__ bih1b, const float* __restrict__ bhh1b,
    const float* __restrict__ fc2w, const float* __restrict__ fc3w)
{
    const int NIN = 16384*256;
    const int NW0 = 4096*256;
    const int NW1 = 4096*1024;
    const int NWH = 2048*512;
    const int e0 = NIN;                 // inb
    const int e1 = e0 + NW0;            // W0m
    const int e2 = e1 + NW1;            // W1m
    const int e3 = e2 + 4*NWH;          // Wh x4
    const int e4 = e3 + 4096;           // b0m
    const int e5 = e4 + 4096;           // b1m
    const int e6 = e5 + 256*512;        // fc2
    const int e7 = e6 + 48*256;         // fc3
    const int total = e7 + 66;          // ctrl
    int stride = gridDim.x * blockDim.x;
    for (int i = blockIdx.x*blockDim.x + threadIdx.x; i < total; i += stride){
        if (i < e0){
            d_inb[i] = __float2bfloat16_rn(inputs[i]);
        } else if (i < e1){
            int j = i - e0;
            int np = j >> 8, k = j & 255;
            int np2 = np & 2047;
            int sr = (np2 & 3)*512 + (np2 >> 2);
            const float* src = (np < 2048) ? Wih0f : Wih0b;
            d_W0m[j] = __float2bfloat16_rn(src[sr*256 + k]);
        } else if (i < e2){
            int j = i - e1;
            int np = j >> 10, k = j & 1023;
            int np2 = np & 2047;
            int sr = (np2 & 3)*512 + (np2 >> 2);
            const float* src = (np < 2048) ? Wih1f : Wih1b;
            d_W1m[j] = __float2bfloat16_rn(src[sr*1024 + k]);
        } else if (i < e3){
            int j = i - e2;
            int arr = j / NWH;
            int jj = j - arr*NWH;
            int np = jj >> 9, k = jj & 511;
            int sr = (np & 3)*512 + (np >> 2);
            const float* src = (arr==0)?Whh0f:(arr==1)?Whh0b:(arr==2)?Whh1f:Whh1b;
            bf16* dst = (arr==0)?d_Wh0f:(arr==1)?d_Wh0b:(arr==2)?d_Wh1f:d_Wh1b;
            dst[jj] = __float2bfloat16_rn(src[sr*512 + k]);
        } else if (i < e4){
            int np = i - e3;
            int np2 = np & 2047;
            int sr = (np2 & 3)*512 + (np2 >> 2);
            d_b0m[np] = (np < 2048) ? (bih0f[sr] + bhh0f[sr]) : (bih0b[sr] + bhh0b[sr]);
        } else if (i < e5){
            int np = i - e4;
            int np2 = np & 2047;
            int sr = (np2 & 3)*512 + (np2 >> 2);
            d_b1m[np] = (np < 2048) ? (bih1f[sr] + bhh1f[sr]) : (bih1b[sr] + bhh1b[sr]);
        } else if (i < e6){
            int j = i - e5;
            d_fc2wB[j] = __float2bfloat16_rn(fc2w[j]);
        } else if (i < e7){
            int j = i - e6;
            d_fc3wB[j] = __float2bfloat16_rn(fc3w[j]);
        } else {
            int j = i - e7;
            if (j < 64) ((volatile int*)d_slot)[j] = 0;
            else d_genv[j - 64] = 0;
        }
    }
}

// fold BN into fc1
__global__ void prep_fc(const float* __restrict__ fc1w, const float* __restrict__ fc1b,
                        const float* __restrict__ gamma, const float* __restrict__ beta,
                        const float* __restrict__ mean, const float* __restrict__ var)
{
    __shared__ float red[256];
    int r = blockIdx.x;
    int tid = threadIdx.x;
    float part = 0.f;
    for (int c = tid; c < 1024; c += 256){
        float sc = gamma[c] * rsqrtf(var[c] + 1e-5f);
        float tc = beta[c] - mean[c]*sc;
        float w = fc1w[r*1024 + c];
        d_fc1wP[r*1024 + c] = __float2bfloat16_rn(w * sc);
        part += w * tc;
    }
    red[tid] = part;
    __syncthreads();
    for (int off = 128; off > 0; off >>= 1){
        if (tid < off) red[tid] += red[tid + off];
        __syncthreads();
    }
    if (tid == 0) d_fc1bP[r] = fc1b[r] + red[0];
}

// ------------------- bf16 GEMM: C = A(MxK) @ W(NxK)^T + bias -------------------
#define BRS 40
__global__ __launch_bounds__(256) void gemm_bf16(
    const bf16* __restrict__ A, const bf16* __restrict__ W,
    const float* __restrict__ bias, void* __restrict__ Cv,
    int M, int N, int K, int relu, int outBf)
{
    extern __shared__ bf16 smb[];
    bf16* As = smb;                 // [2][128][BRS]
    bf16* Bs = smb + 2*128*BRS;     // [2][128][BRS]
    int tid  = threadIdx.x;
    int warp = tid >> 5, lane = tid & 31;
    int wm = warp >> 2, wn = warp & 3;
    int g = lane >> 2, tg = lane & 3;
    int m0 = blockIdx.y*128, n0 = blockIdx.x*128;

    float acc[4][4][4];
#pragma unroll
    for (int a = 0; a < 4; a++)
#pragma unroll
        for (int b = 0; b < 4; b++)
#pragma unroll
            for (int c = 0; c < 4; c++) acc[a][b][c] = 0.f;

    int KT = K >> 5;

    auto stage = [&](int kt, int bb){
        const bf16* Ag = A + (size_t)m0*K + kt*32;
#pragma unroll
        for (int i = 0; i < 2; i++){
            int q = i*256 + tid;
            int r = q >> 2;
            int c = (q & 3) * 8;
            cp16(&As[bb*128*BRS + r*BRS + c], Ag + (size_t)r*K + c);
        }
        const bf16* Wg = W + kt*32;
#pragma unroll
        for (int i = 0; i < 2; i++){
            int q = i*256 + tid;
            int r = q >> 2;
            int c = (q & 3) * 8;
            int nr = n0 + r;
            int nc = nr < N ? nr : 0;
            cp16z(&Bs[bb*128*BRS + r*BRS + c], Wg + (size_t)nc*K + c, nr < N);
        }
        cp_commit();
    };

    stage(0, 0);
    if (KT > 1) stage(1, 1);

    for (int kt = 0; kt < KT; kt++){
        if (kt < KT-1) cp_wait1(); else cp_wait0();
        __syncthreads();
        int bb = kt & 1;
        const bf16* Ab = As + bb*128*BRS + (wm*64)*BRS;
        const bf16* Bb = Bs + bb*128*BRS + (wn*32)*BRS;
#pragma unroll
        for (int kk = 0; kk < 2; kk++){
            int kc = kk*16 + tg*2;
            unsigned af[4][4], bf[4][2];
#pragma unroll
            for (int mt = 0; mt < 4; mt++){
                const bf16* p = Ab + (mt*16 + g)*BRS + kc;
                af[mt][0] = *(const unsigned*)p;
                af[mt][1] = *(const unsigned*)(p + 8*BRS);
                af[mt][2] = *(const unsigned*)(p + 8);
                af[mt][3] = *(const unsigned*)(p + 8*BRS + 8);
            }
#pragma unroll
            for (int nt = 0; nt < 4; nt++){
                const bf16* p = Bb + (nt*8 + g)*BRS + kc;
                bf[nt][0] = *(const unsigned*)p;
                bf[nt][1] = *(const unsigned*)(p + 8);
            }
#pragma unroll
            for (int mt = 0; mt < 4; mt++)
#pragma unroll
                for (int nt = 0; nt < 4; nt++)
                    mma16(acc[mt][nt], af[mt], bf[nt]);
        }
        __syncthreads();
        if (kt + 2 < KT) stage(kt+2, bb);
    }

#pragma unroll
    for (int mt = 0; mt < 4; mt++){
        int row = m0 + wm*64 + mt*16 + g;
#pragma unroll
        for (int nt = 0; nt < 4; nt++){
            int col = n0 + wn*32 + nt*8 + 2*tg;
            if (col < N){
                float b0 = bias[col], b1 = bias[col+1];
                float v0 = acc[mt][nt][0] + b0;
                float v1 = acc[mt][nt][1] + b1;
                float v2 = acc[mt][nt][2] + b0;
                float v3 = acc[mt][nt][3] + b1;
                if (relu){
                    v0 = fmaxf(v0, 0.f); v1 = fmaxf(v1, 0.f);
                    v2 = fmaxf(v2, 0.f); v3 = fmaxf(v3, 0.f);
                }
                if (outBf){
                    bf16* C16 = (bf16*)Cv;
                    *(bf162*)&C16[(size_t)row*N + col]     = __floats2bfloat162_rn(v0, v1);
                    *(bf162*)&C16[(size_t)(row+8)*N + col] = __floats2bfloat162_rn(v2, v3);
                } else {
                    float* C = (float*)Cv;
                    *(float2*)&C[(size_t)row*N + col]     = make_float2(v0, v1);
                    *(float2*)&C[(size_t)(row+8)*N + col] = make_float2(v2, v3);
                }
            }
        }
    }
}

// ------------------- persistent bidirectional LSTM layer (bf16 recurrence) -------------------
// 64 blocks x 256 threads. dir = bx>>5, ns = bx&31. Block owns gate cols [ns*64,+64)
// (gate-interleaved) of its direction = hidden units [ns*16,+16).
#define WSB 520     // padded bf16 row stride for whh_s / h_s (conflict-free)
__global__ __launch_bounds__(256) void lstm_layer(
    const bf16* __restrict__ pre,
    const bf16* __restrict__ whhF, const bf16* __restrict__ whhB,
    bf16* __restrict__ out, int gen0)
{
    extern __shared__ char smraw[];
    bf16* whh_s = (bf16*)smraw;                  // [64][WSB]
    bf16* h_s   = whh_s + 64*WSB;                // [64][WSB]
    bf16* pre_s = h_s + 64*WSB;                  // [64][64]
    float* G_s  = (float*)(pre_s + 64*64);       // [64][68]
    float* c_s  = G_s + 64*68;                   // [64][16]

    int tid = threadIdx.x;
    int warp = tid >> 5, lane = tid & 31;
    int wm = warp >> 2, wn = warp & 3;           // 2(m) x 4(n) warps; warp tile 32(m) x 16(n)
    int g = lane >> 2, tg = lane & 3;
    int dir = blockIdx.x >> 5;
    int ns  = blockIdx.x & 31;
    int n0  = ns*64;
    int j0  = ns*16;
    const bf16* whh = dir ? whhB : whhF;

    // persistent Whh slice (bf16, padded stride)
#pragma unroll
    for (int i = 0; i < 16; i++){
        int q = i*256 + tid;          // 0..4095
        int r = q >> 6;               // 0..63 (gate col)
        int c = (q & 63) * 8;         // 0..504
        cp16(&whh_s[r*WSB + c], &whh[(n0 + r)*512 + c]);
    }
    cp_commit();
    for (int q = tid; q < 64*16; q += 256) c_s[q] = 0.f;
    cp_wait0();
    __syncthreads();

    int ub = tid >> 2;            // batch 0..63
    int uu = (tid & 3)*4;         // first of 4 units

    for (int s = 0; s < SEQ; s++){
        int t  = dir ? (SEQ-1 - s) : s;
        int rp = s & 1;
        int wp = rp ^ 1;

        // --- stage h (group A) and pre (group B) ---
        if (s > 0){
            const bf16* hsrc = d_hbuf + (size_t)(rp*2 + dir)*BATCH*HID;
#pragma unroll
            for (int i = 0; i < 16; i++){
                int q = i*256 + tid;
                int r = q >> 6;
                int c = (q & 63) * 8;
                cp16(&h_s[r*WSB + c], &hsrc[r*HID + c]);
            }
            cp_commit();
        }
#pragma unroll
        for (int i = 0; i < 2; i++){
            int q = i*256 + tid;          // 0..511
            int r = q >> 3;               // batch
            int c = (q & 7) * 8;          // 0..56
            cp16(&pre_s[r*64 + c], &pre[((size_t)(r*SEQ + t))*4096 + dir*2048 + n0 + c]);
        }
        cp_commit();

        float acc[2][2][4];
#pragma unroll
        for (int a = 0; a < 2; a++)
#pragma unroll
            for (int b = 0; b < 2; b++)
#pragma unroll
                for (int c = 0; c < 4; c++) acc[a][b][c] = 0.f;

        if (s > 0){
            cp_wait1();         // h ready (pre may still be in flight)
            __syncthreads();
            const bf16* Ab = h_s + (wm*32)*WSB;
            const bf16* Bb = whh_s + (wn*16)*WSB;
#pragma unroll 8
            for (int k16 = 0; k16 < 32; k16++){
                int kc = k16*16 + tg*2;
                unsigned af[2][4], bfr[2][2];
#pragma unroll
                for (int mt = 0; mt < 2; mt++){
                    const bf16* p = Ab + (mt*16 + g)*WSB + kc;
                    af[mt][0] = *(const unsigned*)p;
                    af[mt][1] = *(const unsigned*)(p + 8*WSB);
                    af[mt][2] = *(const unsigned*)(p + 8);
                    af[mt][3] = *(const unsigned*)(p + 8*WSB + 8);
                }
#pragma unroll
                for (int nt = 0; nt < 2; nt++){
                    const bf16* p = Bb + (nt*8 + g)*WSB + kc;
                    bfr[nt][0] = *(const unsigned*)p;
                    bfr[nt][1] = *(const unsigned*)(p + 8);
                }
#pragma unroll
                for (int mt = 0; mt < 2; mt++)
#pragma unroll
                    for (int nt = 0; nt < 2; nt++)
                        mma16(acc[mt][nt], af[mt], bfr[nt]);
            }
        }

        // dump accumulators (rows = batch, cols = gate)
#pragma unroll
        for (int mt = 0; mt < 2; mt++){
            int rr = wm*32 + mt*16 + g;
#pragma unroll
            for (int nt = 0; nt < 2; nt++){
                int cc = wn*16 + nt*8 + 2*tg;
                G_s[rr*68 + cc]        = acc[mt][nt][0];
                G_s[rr*68 + cc + 1]    = acc[mt][nt][1];
                G_s[(rr+8)*68 + cc]    = acc[mt][nt][2];
                G_s[(rr+8)*68 + cc+1]  = acc[mt][nt][3];
            }
        }
        cp_wait0();             // pre ready
        __syncthreads();

        // gate update: thread -> batch ub, units uu..uu+3
        {
            bf16* hdst = d_hbuf + (size_t)(wp*2 + dir)*BATCH*HID;
            float hv4[4];
#pragma unroll
            for (int k = 0; k < 4; k++){
                int u = uu + k;
                float4 Gv = *(float4*)&G_s[ub*68 + 4*u];
                bf162 pA = *(bf162*)&pre_s[ub*64 + 4*u];
                bf162 pB = *(bf162*)&pre_s[ub*64 + 4*u + 2];
                float iv = Gv.x + __low2float(pA);
                float fv = Gv.y + __high2float(pA);
                float gv = Gv.z + __low2float(pB);
                float ov = Gv.w + __high2float(pB);
                float co = c_s[ub*16 + u];
                float si = 1.f/(1.f + __expf(-iv));
                float sf = 1.f/(1.f + __expf(-fv));
                float so = 1.f/(1.f + __expf(-ov));
                float cn = sf*co + si*tanhf(gv);
                hv4[k] = so*tanhf(cn);
                c_s[ub*16 + u] = cn;
            }
            bf162 p0 = __floats2bfloat162_rn(hv4[0], hv4[1]);
            bf162 p1 = __floats2bfloat162_rn(hv4[2], hv4[3]);
            uint2 pk = make_uint2(*(unsigned*)&p0, *(unsigned*)&p1);
            *(uint2*)&hdst[ub*HID + j0 + uu] = pk;
            *(uint2*)&out[(size_t)(ub*SEQ + t)*H2 + dir*HID + j0 + uu] = pk;
        }

        // one-hop per-direction barrier
        __syncthreads();
        int target = gen0 + s + 1;
        if (tid == 0){
            __threadfence();
            d_slot[dir][ns] = target;
        }
        if (tid < 32){
            while (d_slot[dir][tid] < target) { }
        }
        __syncthreads();
    }
}

// ------------------- CRF -------------------
__global__ void crf_kernel(const float* __restrict__ em, const int* __restrict__ tags,
                           const float* __restrict__ start, const float* __restrict__ endv,
                           const float* __restrict__ trans, float* __restrict__ v)
{
    __shared__ float tr[NTAG*49];
    __shared__ float al[2][NTAG];
    __shared__ float red[64];
    __shared__ float num_s;
    int b = blockIdx.x;
    int tid = threadIdx.x;
    const int* tg = tags + b*SEQ;
    const float* eb = em + b*SEQ*NTAG;

    for (int q = tid; q < NTAG*NTAG; q += 64){
        int i = q / NTAG, j = q - i*NTAG;
        tr[i*49 + j] = trans[q];
    }
    float part = 0.f;
    for (int t = tid; t < SEQ; t += 64){
        int tt = tg[t];
        part += eb[t*NTAG + tt];
        if (t < SEQ-1) part += trans[tt*NTAG + tg[t+1]];
    }
    red[tid] = part;
    if (tid < NTAG) al[0][tid] = start[tid] + eb[tid];
    __syncthreads();
    if (tid == 0){
        float s = 0.f;
        for (int i = 0; i < 64; i++) s += red[i];
        num_s = s + start[tg[0]] + endv[tg[SEQ-1]];
    }
    __syncthreads();

    for (int t = 1; t < SEQ; t++){
        int cur = t & 1, prv = cur ^ 1;
        float na = 0.f;
        if (tid < NTAG){
            float m = -1e30f;
            for (int i = 0; i < NTAG; i++) m = fmaxf(m, al[prv][i] + tr[i*49 + tid]);
            float ssum = 0.f;
            for (int i = 0; i < NTAG; i++) ssum += __expf(al[prv][i] + tr[i*49 + tid] - m);
            na = m + logf(ssum) + eb[t*NTAG + tid];
        }
        __syncthreads();
        if (tid < NTAG) al[cur][tid] = na;
        __syncthreads();
    }

    if (tid == 0){
        const float* a = al[(SEQ-1) & 1];
        float m = -1e30f;
        for (int j = 0; j < NTAG; j++) m = fmaxf(m, a[j] + endv[j]);
        float s = 0.f;
        for (int j = 0; j < NTAG; j++) s += __expf(a[j] + endv[j] - m);
        v[b] = num_s - (m + logf(s));
    }
}

__global__ void final_reduce(const float* __restrict__ v, float* __restrict__ out){
    __shared__ float s[64];
    s[threadIdx.x] = v[threadIdx.x];
    __syncthreads();
    if (threadIdx.x == 0){
        float a = 0.f;
        for (int i = 0; i < 64; i++) a += s[i];
        out[0] = -(a / 64.f);
    }
}

// ------------------- launch -------------------
extern "C" void kernel_launch(void* const* d_in, const int* in_sizes, int n_in,
                              void* d_out, int out_size)
{
    const float* inputs = (const float*)d_in[0];
    const int*   tags   = (const int*)d_in[1];
    const float *Wih0f=(const float*)d_in[2],  *Whh0f=(const float*)d_in[3],
                *bih0f=(const float*)d_in[4],  *bhh0f=(const float*)d_in[5];
    const float *Wih0b=(const float*)d_in[6],  *Whh0b=(const float*)d_in[7],
                *bih0b=(const float*)d_in[8],  *bhh0b=(const float*)d_in[9];
    const float *Wih1f=(const float*)d_in[10], *Whh1f=(const float*)d_in[11],
                *bih1f=(const float*)d_in[12], *bhh1f=(const float*)d_in[13];
    const float *Wih1b=(const float*)d_in[14], *Whh1b=(const float*)d_in[15],
                *bih1b=(const float*)d_in[16], *bhh1b=(const float*)d_in[17];
    const float *gamma=(const float*)d_in[18], *beta=(const float*)d_in[19],
                *mean=(const float*)d_in[20],  *var=(const float*)d_in[21];
    const float *fc1w=(const float*)d_in[22], *fc1b=(const float*)d_in[23];
    const float *fc2w=(const float*)d_in[24], *fc2b=(const float*)d_in[25];
    const float *fc3w=(const float*)d_in[26], *fc3b=(const float*)d_in[27];
    const float *crfS=(const float*)d_in[28], *crfE=(const float*)d_in[29],
                *crfT=(const float*)d_in[30];

    bf16 *pInb,*pW0m,*pW1m,*pWh0f,*pWh0b,*pWh1f,*pWh1b;
    bf16 *pFc1w,*pFc2w,*pFc3w,*pX1,*pX2,*pF1,*pF2,*pPre;
    float *pB0m,*pB1m,*pFc1b,*pEm,*pV;
    cudaGetSymbolAddress((void**)&pInb, d_inb);
    cudaGetSymbolAddress((void**)&pW0m, d_W0m);
    cudaGetSymbolAddress((void**)&pW1m, d_W1m);
    cudaGetSymbolAddress((void**)&pWh0f, d_Wh0f);
    cudaGetSymbolAddress((void**)&pWh0b, d_Wh0b);
    cudaGetSymbolAddress((void**)&pWh1f, d_Wh1f);
    cudaGetSymbolAddress((void**)&pWh1b, d_Wh1b);
    cudaGetSymbolAddress((void**)&pB0m, d_b0m);
    cudaGetSymbolAddress((void**)&pB1m, d_b1m);
    cudaGetSymbolAddress((void**)&pFc1w, d_fc1wP);
    cudaGetSymbolAddress((void**)&pFc1b, d_fc1bP);
    cudaGetSymbolAddress((void**)&pFc2w, d_fc2wB);
    cudaGetSymbolAddress((void**)&pFc3w, d_fc3wB);
    cudaGetSymbolAddress((void**)&pPre, d_pre);
    cudaGetSymbolAddress((void**)&pX1, d_x1);
    cudaGetSymbolAddress((void**)&pX2, d_x2);
    cudaGetSymbolAddress((void**)&pF1, d_f1);
    cudaGetSymbolAddress((void**)&pF2, d_f2);
    cudaGetSymbolAddress((void**)&pEm, d_em);
    cudaGetSymbolAddress((void**)&pV, d_v);

    const int gemm_smem = 2*2*128*BRS*2;
    const int lstm_smem = (2*64*WSB + 64*64)*2 + (64*68 + 64*16)*4;
    cudaFuncSetAttribute(gemm_bf16, cudaFuncAttributeMaxDynamicSharedMemorySize, gemm_smem);
    cudaFuncSetAttribute(lstm_layer, cudaFuncAttributeMaxDynamicSharedMemorySize, lstm_smem);

    // 0: prep_all (also resets barrier slots for every graph replay)
    prep_all<<<2048,256>>>(inputs, Wih0f, Wih0b, Whh0f, Whh0b, Wih1f, Wih1b, Whh1f, Whh1b,
                           bih0f, bhh0f, bih0b, bhh0b, bih1f, bhh1f, bih1b, bhh1b,
                           fc2w, fc3w);
    // 1: prep_fc
    prep_fc<<<512,256>>>(fc1w, fc1b, gamma, beta, mean, var);
    // 2: layer-0 projection (bf16 pre)
    gemm_bf16<<<dim3(32,128),256,gemm_smem>>>(pInb, pW0m, pB0m, pPre, MROWS, 4096, 256, 0, 1);
    // 3: layer-0 recurrence (targets 1..256)
    lstm_layer<<<64,256,lstm_smem>>>(pPre, pWh0f, pWh0b, pX1, 0);
    // 4: layer-1 projection
    gemm_bf16<<<dim3(32,128),256,gemm_smem>>>(pX1, pW1m, pB1m, pPre, MROWS, 4096, 1024, 0, 1);
    // 5: layer-1 recurrence (targets 257..512; slots monotonic, no reset needed)
    lstm_layer<<<64,256,lstm_smem>>>(pPre, pWh1f, pWh1b, pX2, 256);
    // 6-8: head (BN folded into fc1)
    gemm_bf16<<<dim3(4,128),256,gemm_smem>>>(pX2, pFc1w, pFc1b, pF1, MROWS, 512, 1024, 1, 1);
    gemm_bf16<<<dim3(2,128),256,gemm_smem>>>(pF1, pFc2w, fc2b, pF2, MROWS, 256, 512, 1, 1);
    gemm_bf16<<<dim3(1,128),256,gemm_smem>>>(pF2, pFc3w, fc3b, pEm, MROWS, NTAG, 256, 0, 0);
    // 9-10: CRF + reduce
    crf_kernel<<<64,64>>>(pEm, tags, crfS, crfE, crfT, pV);
    final_reduce<<<1,64>>>(pV, (float*)d_out);
}

// round 6
// speedup vs baseline: 3.6566x; 1.4164x over previous
#include <cuda_runtime.h>
#include <cuda_bf16.h>
#include <cstdint>

#define BATCH 64
#define SEQ   256
#define HID   512
#define NTAG  48
#define MROWS (BATCH*SEQ)     // 16384
#define G4    2048
#define H2    1024

typedef __nv_bfloat16 bf16;
typedef __nv_bfloat162 bf162;

// ------------------- static device scratch -------------------
__device__ bf16  d_inb[16384*256];
__device__ bf16  d_W0m[4096*256];
__device__ bf16  d_W1m[4096*1024];
__device__ bf16  d_Wh0f[2048*512];
__device__ bf16  d_Wh0b[2048*512];
__device__ bf16  d_Wh1f[2048*512];
__device__ bf16  d_Wh1b[2048*512];
__device__ float d_b0m[4096];
__device__ float d_b1m[4096];
__device__ bf16  d_fc1wP[512*1024];
__device__ float d_fc1bP[512];
__device__ bf16  d_fc2wB[256*512];
__device__ bf16  d_fc3wB[48*256];
__device__ bf16  d_pre[(size_t)16384*4096];
__device__ bf16  d_x1[16384*1024];
__device__ bf16  d_x2[16384*1024];
__device__ bf16  d_f1[16384*512];
__device__ bf16  d_f2[16384*256];
__device__ float d_em[16384*48];
__device__ bf16  d_hbuf[2*2*BATCH*HID];   // [parity][dir][b][j]
__device__ float d_v[64];
__device__ volatile int d_slot[2][256];   // padded: slot ns at index ns*8 (32B stride)
__device__ volatile int d_genv[2];

// ------------------- helpers -------------------
__device__ __forceinline__ void mma16r(float* c,
    unsigned a0, unsigned a1, unsigned a2, unsigned a3, unsigned b0, unsigned b1){
    asm volatile(
        "mma.sync.aligned.m16n8k16.row.col.f32.bf16.bf16.f32 "
        "{%0,%1,%2,%3}, {%4,%5,%6,%7}, {%8,%9}, {%0,%1,%2,%3};\n"
        : "+f"(c[0]), "+f"(c[1]), "+f"(c[2]), "+f"(c[3])
        : "r"(a0), "r"(a1), "r"(a2), "r"(a3), "r"(b0), "r"(b1));
}

__device__ __forceinline__ void ldsm4(unsigned& r0, unsigned& r1, unsigned& r2, unsigned& r3,
                                      unsigned addr){
    asm volatile("ldmatrix.sync.aligned.m8n8.x4.shared.b16 {%0,%1,%2,%3}, [%4];"
        : "=r"(r0), "=r"(r1), "=r"(r2), "=r"(r3) : "r"(addr));
}

__device__ __forceinline__ float fsig(float x){
    float t;
    asm("mul.f32 %0, %1, 0fBFB8AA3B;" : "=f"(t) : "f"(x));   // -x*log2(e)
    asm("ex2.approx.f32 %0, %0;" : "+f"(t));
    asm("add.f32 %0, %0, 0f3F800000;" : "+f"(t));
    asm("rcp.approx.f32 %0, %0;" : "+f"(t));
    return t;
}
__device__ __forceinline__ float ftanh(float x){
    float r; asm("tanh.approx.f32 %0, %1;" : "=f"(r) : "f"(x)); return r;
}

__device__ __forceinline__ void cp16(void* smem, const void* gmem){
    unsigned sa = (unsigned)__cvta_generic_to_shared(smem);
    asm volatile("cp.async.cg.shared.global [%0], [%1], 16;" :: "r"(sa), "l"(gmem));
}
__device__ __forceinline__ void cp16z(void* smem, const void* gmem, int pred){
    unsigned sa = (unsigned)__cvta_generic_to_shared(smem);
    int bytes = pred ? 16 : 0;
    asm volatile("cp.async.cg.shared.global [%0], [%1], 16, %2;" :: "r"(sa), "l"(gmem), "r"(bytes));
}
__device__ __forceinline__ void cp_commit(){ asm volatile("cp.async.commit_group;"); }
__device__ __forceinline__ void cp_wait0(){ asm volatile("cp.async.wait_group 0;"); }
__device__ __forceinline__ void cp_wait1(){ asm volatile("cp.async.wait_group 1;"); }

// ------------------- prep -------------------
__global__ void prep_all(
    const float* __restrict__ inputs,
    const float* __restrict__ Wih0f, const float* __restrict__ Wih0b,
    const float* __restrict__ Whh0f, const float* __restrict__ Whh0b,
    const float* __restrict__ Wih1f, const float* __restrict__ Wih1b,
    const float* __restrict__ Whh1f, const float* __restrict__ Whh1b,
    const float* __restrict__ bih0f, const float* __restrict__ bhh0f,
    const float* __restrict__ bih0b, const float* __restrict__ bhh0b,
    const float* __restrict__ bih1f, const float* __restrict__ bhh1f,
    const float* __restrict__ bih1b, const float* __restrict__ bhh1b,
    const float* __restrict__ fc2w, const float* __restrict__ fc3w)
{
    const int NIN = 16384*256;
    const int NW0 = 4096*256;
    const int NW1 = 4096*1024;
    const int NWH = 2048*512;
    const int e0 = NIN;
    const int e1 = e0 + NW0;
    const int e2 = e1 + NW1;
    const int e3 = e2 + 4*NWH;
    const int e4 = e3 + 4096;
    const int e5 = e4 + 4096;
    const int e6 = e5 + 256*512;
    const int e7 = e6 + 48*256;
    const int total = e7 + 514;         // ctrl: 512 slots + 2 genv
    int stride = gridDim.x * blockDim.x;
    for (int i = blockIdx.x*blockDim.x + threadIdx.x; i < total; i += stride){
        if (i < e0){
            d_inb[i] = __float2bfloat16_rn(inputs[i]);
        } else if (i < e1){
            int j = i - e0;
            int np = j >> 8, k = j & 255;
            int np2 = np & 2047;
            int sr = (np2 & 3)*512 + (np2 >> 2);
            const float* src = (np < 2048) ? Wih0f : Wih0b;
            d_W0m[j] = __float2bfloat16_rn(src[sr*256 + k]);
        } else if (i < e2){
            int j = i - e1;
            int np = j >> 10, k = j & 1023;
            int np2 = np & 2047;
            int sr = (np2 & 3)*512 + (np2 >> 2);
            const float* src = (np < 2048) ? Wih1f : Wih1b;
            d_W1m[j] = __float2bfloat16_rn(src[sr*1024 + k]);
        } else if (i < e3){
            int j = i - e2;
            int arr = j / NWH;
            int jj = j - arr*NWH;
            int np = jj >> 9, k = jj & 511;
            int sr = (np & 3)*512 + (np >> 2);
            const float* src = (arr==0)?Whh0f:(arr==1)?Whh0b:(arr==2)?Whh1f:Whh1b;
            bf16* dst = (arr==0)?d_Wh0f:(arr==1)?d_Wh0b:(arr==2)?d_Wh1f:d_Wh1b;
            dst[jj] = __float2bfloat16_rn(src[sr*512 + k]);
        } else if (i < e4){
            int np = i - e3;
            int np2 = np & 2047;
            int sr = (np2 & 3)*512 + (np2 >> 2);
            d_b0m[np] = (np < 2048) ? (bih0f[sr] + bhh0f[sr]) : (bih0b[sr] + bhh0b[sr]);
        } else if (i < e5){
            int np = i - e4;
            int np2 = np & 2047;
            int sr = (np2 & 3)*512 + (np2 >> 2);
            d_b1m[np] = (np < 2048) ? (bih1f[sr] + bhh1f[sr]) : (bih1b[sr] + bhh1b[sr]);
        } else if (i < e6){
            int j = i - e5;
            d_fc2wB[j] = __float2bfloat16_rn(fc2w[j]);
        } else if (i < e7){
            int j = i - e6;
            d_fc3wB[j] = __float2bfloat16_rn(fc3w[j]);
        } else {
            int j = i - e7;
            if (j < 512) ((volatile int*)d_slot)[j] = 0;
            else d_genv[j - 512] = 0;
        }
    }
}

// fold BN into fc1
__global__ void prep_fc(const float* __restrict__ fc1w, const float* __restrict__ fc1b,
                        const float* __restrict__ gamma, const float* __restrict__ beta,
                        const float* __restrict__ mean, const float* __restrict__ var)
{
    __shared__ float red[256];
    int r = blockIdx.x;
    int tid = threadIdx.x;
    float part = 0.f;
    for (int c = tid; c < 1024; c += 256){
        float sc = gamma[c] * rsqrtf(var[c] + 1e-5f);
        float tc = beta[c] - mean[c]*sc;
        float w = fc1w[r*1024 + c];
        d_fc1wP[r*1024 + c] = __float2bfloat16_rn(w * sc);
        part += w * tc;
    }
    red[tid] = part;
    __syncthreads();
    for (int off = 128; off > 0; off >>= 1){
        if (tid < off) red[tid] += red[tid + off];
        __syncthreads();
    }
    if (tid == 0) d_fc1bP[r] = fc1b[r] + red[0];
}

// ------------------- bf16 GEMM: C = A(MxK) @ W(NxK)^T + bias -------------------
#define BRS 40
__global__ __launch_bounds__(256) void gemm_bf16(
    const bf16* __restrict__ A, const bf16* __restrict__ W,
    const float* __restrict__ bias, void* __restrict__ Cv,
    int M, int N, int K, int relu, int outBf)
{
    extern __shared__ bf16 smb[];
    bf16* As = smb;
    bf16* Bs = smb + 2*128*BRS;
    int tid  = threadIdx.x;
    int warp = tid >> 5, lane = tid & 31;
    int wm = warp >> 2, wn = warp & 3;
    int g = lane >> 2, tg = lane & 3;
    int m0 = blockIdx.y*128, n0 = blockIdx.x*128;

    float acc[4][4][4];
#pragma unroll
    for (int a = 0; a < 4; a++)
#pragma unroll
        for (int b = 0; b < 4; b++)
#pragma unroll
            for (int c = 0; c < 4; c++) acc[a][b][c] = 0.f;

    int KT = K >> 5;

    auto stage = [&](int kt, int bb){
        const bf16* Ag = A + (size_t)m0*K + kt*32;
#pragma unroll
        for (int i = 0; i < 2; i++){
            int q = i*256 + tid;
            int r = q >> 2;
            int c = (q & 3) * 8;
            cp16(&As[bb*128*BRS + r*BRS + c], Ag + (size_t)r*K + c);
        }
        const bf16* Wg = W + kt*32;
#pragma unroll
        for (int i = 0; i < 2; i++){
            int q = i*256 + tid;
            int r = q >> 2;
            int c = (q & 3) * 8;
            int nr = n0 + r;
            int nc = nr < N ? nr : 0;
            cp16z(&Bs[bb*128*BRS + r*BRS + c], Wg + (size_t)nc*K + c, nr < N);
        }
        cp_commit();
    };

    stage(0, 0);
    if (KT > 1) stage(1, 1);

    for (int kt = 0; kt < KT; kt++){
        if (kt < KT-1) cp_wait1(); else cp_wait0();
        __syncthreads();
        int bb = kt & 1;
        const bf16* Ab = As + bb*128*BRS + (wm*64)*BRS;
        const bf16* Bb = Bs + bb*128*BRS + (wn*32)*BRS;
#pragma unroll
        for (int kk = 0; kk < 2; kk++){
            int kc = kk*16 + tg*2;
            unsigned af[4][4], bf[4][2];
#pragma unroll
            for (int mt = 0; mt < 4; mt++){
                const bf16* p = Ab + (mt*16 + g)*BRS + kc;
                af[mt][0] = *(const unsigned*)p;
                af[mt][1] = *(const unsigned*)(p + 8*BRS);
                af[mt][2] = *(const unsigned*)(p + 8);
                af[mt][3] = *(const unsigned*)(p + 8*BRS + 8);
            }
#pragma unroll
            for (int nt = 0; nt < 4; nt++){
                const bf16* p = Bb + (nt*8 + g)*BRS + kc;
                bf[nt][0] = *(const unsigned*)p;
                bf[nt][1] = *(const unsigned*)(p + 8);
            }
#pragma unroll
            for (int mt = 0; mt < 4; mt++)
#pragma unroll
                for (int nt = 0; nt < 4; nt++)
                    mma16r(acc[mt][nt], af[mt][0], af[mt][1], af[mt][2], af[mt][3],
                           bf[nt][0], bf[nt][1]);
        }
        __syncthreads();
        if (kt + 2 < KT) stage(kt+2, bb);
    }

#pragma unroll
    for (int mt = 0; mt < 4; mt++){
        int row = m0 + wm*64 + mt*16 + g;
#pragma unroll
        for (int nt = 0; nt < 4; nt++){
            int col = n0 + wn*32 + nt*8 + 2*tg;
            if (col < N){
                float b0 = bias[col], b1 = bias[col+1];
                float v0 = acc[mt][nt][0] + b0;
                float v1 = acc[mt][nt][1] + b1;
                float v2 = acc[mt][nt][2] + b0;
                float v3 = acc[mt][nt][3] + b1;
                if (relu){
                    v0 = fmaxf(v0, 0.f); v1 = fmaxf(v1, 0.f);
                    v2 = fmaxf(v2, 0.f); v3 = fmaxf(v3, 0.f);
                }
                if (outBf){
                    bf16* C16 = (bf16*)Cv;
                    *(bf162*)&C16[(size_t)row*N + col]     = __floats2bfloat162_rn(v0, v1);
                    *(bf162*)&C16[(size_t)(row+8)*N + col] = __floats2bfloat162_rn(v2, v3);
                } else {
                    float* C = (float*)Cv;
                    *(float2*)&C[(size_t)row*N + col]     = make_float2(v0, v1);
                    *(float2*)&C[(size_t)(row+8)*N + col] = make_float2(v2, v3);
                }
            }
        }
    }
}

// ------------------- persistent bidirectional LSTM layer (bf16, ldmatrix) -------------------
// 64 blocks x 256 threads. dir = bx>>5, ns = bx&31. Block owns gate cols [ns*64,+64).
#define WSB 520
__global__ __launch_bounds__(256) void lstm_layer(
    const bf16* __restrict__ pre,
    const bf16* __restrict__ whhF, const bf16* __restrict__ whhB,
    bf16* __restrict__ out, int gen0)
{
    extern __shared__ char smraw[];
    bf16* whh_s = (bf16*)smraw;                  // [64][WSB]
    bf16* h_s   = whh_s + 64*WSB;                // [64][WSB]
    bf16* pre_s = h_s + 64*WSB;                  // [2][64][64]
    float* G_s  = (float*)(pre_s + 2*64*64);     // [64][68]
    float* c_s  = G_s + 64*68;                   // [64][16]

    int tid = threadIdx.x;
    int warp = tid >> 5, lane = tid & 31;
    int wm = warp >> 2, wn = warp & 3;           // 2(m) x 4(n); warp tile 32(batch) x 16(gate)
    int g = lane >> 2, tg = lane & 3;
    int dir = blockIdx.x >> 5;
    int ns  = blockIdx.x & 31;
    int n0  = ns*64;
    int j0  = ns*16;
    const bf16* whh = dir ? whhB : whhF;

    // persistent Whh slice
#pragma unroll
    for (int i = 0; i < 16; i++){
        int q = i*256 + tid;
        int r = q >> 6;
        int c = (q & 63) * 8;
        cp16(&whh_s[r*WSB + c], &whh[(n0 + r)*512 + c]);
    }
    cp_commit();
    for (int q = tid; q < 64*16; q += 256) c_s[q] = 0.f;
    cp_wait0();
    __syncthreads();

    // ldmatrix lane addresses (invariant across steps)
    int lrow = lane & 15;
    int lcol = (lane >> 4) * 16;                 // byte offset within 32B k-slab
    unsigned hbase = (unsigned)__cvta_generic_to_shared(h_s);
    unsigned wbase = (unsigned)__cvta_generic_to_shared(whh_s);
    unsigned aAddr0 = hbase + (unsigned)((wm*32 + lrow)*WSB)*2u + lcol;
    unsigned aAddr1 = aAddr0 + 16u*WSB*2u;
    unsigned bAddr  = wbase + (unsigned)((wn*16 + lrow)*WSB)*2u + lcol;

    int ub = tid >> 2;            // batch 0..63
    int uu = (tid & 3)*4;         // first of 4 units

    // prefetch pre for step 0
    {
        int t0 = dir ? (SEQ-1) : 0;
#pragma unroll
        for (int i = 0; i < 2; i++){
            int q = i*256 + tid;
            int r = q >> 3;
            int c = (q & 7) * 8;
            cp16(&pre_s[r*64 + c], &pre[((size_t)(r*SEQ + t0))*4096 + dir*2048 + n0 + c]);
        }
        cp_commit();
    }

    for (int s = 0; s < SEQ; s++){
        int t  = dir ? (SEQ-1 - s) : s;
        int rp = s & 1;
        int wp = rp ^ 1;

        // stage h for this step
        if (s > 0){
            const bf16* hsrc = d_hbuf + (size_t)(rp*2 + dir)*BATCH*HID;
#pragma unroll
            for (int i = 0; i < 16; i++){
                int q = i*256 + tid;
                int r = q >> 6;
                int c = (q & 63) * 8;
                cp16(&h_s[r*WSB + c], &hsrc[r*HID + c]);
            }
            cp_commit();
        }
        // prefetch pre for step s+1 (always commit, possibly empty group)
        {
            int sn = s + 1;
            if (sn < SEQ){
                int tn = dir ? (SEQ-1 - sn) : sn;
                bf16* pb = pre_s + (sn & 1)*4096;
#pragma unroll
                for (int i = 0; i < 2; i++){
                    int q = i*256 + tid;
                    int r = q >> 3;
                    int c = (q & 7) * 8;
                    cp16(&pb[r*64 + c], &pre[((size_t)(r*SEQ + tn))*4096 + dir*2048 + n0 + c]);
                }
            }
            cp_commit();
        }

        float acc[2][2][4];
#pragma unroll
        for (int a = 0; a < 2; a++)
#pragma unroll
            for (int b = 0; b < 2; b++)
#pragma unroll
                for (int c = 0; c < 4; c++) acc[a][b][c] = 0.f;

        cp_wait1();                 // h_s + pre_s ready (next-step pre may pend)
        __syncthreads();

        if (s > 0){
#pragma unroll 8
            for (int k16 = 0; k16 < 32; k16++){
                unsigned off = (unsigned)k16 * 32u;
                unsigned a0,a1,a2,a3, c0,c1,c2,c3, b0,b1,b2,b3;
                ldsm4(a0,a1,a2,a3, aAddr0 + off);
                ldsm4(c0,c1,c2,c3, aAddr1 + off);
                ldsm4(b0,b1,b2,b3, bAddr + off);
                mma16r(acc[0][0], a0,a1,a2,a3, b0,b2);
                mma16r(acc[0][1], a0,a1,a2,a3, b1,b3);
                mma16r(acc[1][0], c0,c1,c2,c3, b0,b2);
                mma16r(acc[1][1], c0,c1,c2,c3, b1,b3);
            }
        }

        // dump accumulators (rows = batch, cols = gate)
#pragma unroll
        for (int mt = 0; mt < 2; mt++){
            int rr = wm*32 + mt*16 + g;
#pragma unroll
            for (int nt = 0; nt < 2; nt++){
                int cc = wn*16 + nt*8 + 2*tg;
                G_s[rr*68 + cc]        = acc[mt][nt][0];
                G_s[rr*68 + cc + 1]    = acc[mt][nt][1];
                G_s[(rr+8)*68 + cc]    = acc[mt][nt][2];
                G_s[(rr+8)*68 + cc+1]  = acc[mt][nt][3];
            }
        }
        __syncthreads();

        // gate update
        {
            const bf16* pcur = pre_s + (s & 1)*4096;
            bf16* hdst = d_hbuf + (size_t)(wp*2 + dir)*BATCH*HID;
            float hv4[4];
#pragma unroll
            for (int k = 0; k < 4; k++){
                int u = uu + k;
                float4 Gv = *(float4*)&G_s[ub*68 + 4*u];
                bf162 pA = *(bf162*)&pcur[ub*64 + 4*u];
                bf162 pB = *(bf162*)&pcur[ub*64 + 4*u + 2];
                float iv = Gv.x + __low2float(pA);
                float fv = Gv.y + __high2float(pA);
                float gv = Gv.z + __low2float(pB);
                float ov = Gv.w + __high2float(pB);
                float co = c_s[ub*16 + u];
                float cn = fsig(fv)*co + fsig(iv)*ftanh(gv);
                hv4[k] = fsig(ov)*ftanh(cn);
                c_s[ub*16 + u] = cn;
            }
            bf162 p0 = __floats2bfloat162_rn(hv4[0], hv4[1]);
            bf162 p1 = __floats2bfloat162_rn(hv4[2], hv4[3]);
            uint2 pk = make_uint2(*(unsigned*)&p0, *(unsigned*)&p1);
            *(uint2*)&hdst[ub*HID + j0 + uu] = pk;
            *(uint2*)&out[(size_t)(ub*SEQ + t)*H2 + dir*HID + j0 + uu] = pk;
        }

        // one-hop per-direction barrier (padded slots)
        __syncthreads();
        int target = gen0 + s + 1;
        if (tid == 0){
            __threadfence();
            d_slot[dir][ns*8] = target;
        }
        if (tid < 32){
            while (d_slot[dir][tid*8] < target) { }
        }
        __syncthreads();
    }
}

// ------------------- CRF -------------------
__global__ void crf_kernel(const float* __restrict__ em, const int* __restrict__ tags,
                           const float* __restrict__ start, const float* __restrict__ endv,
                           const float* __restrict__ trans, float* __restrict__ v)
{
    __shared__ float tr[NTAG*49];
    __shared__ float al[2][NTAG];
    __shared__ float red[64];
    __shared__ float num_s;
    int b = blockIdx.x;
    int tid = threadIdx.x;
    const int* tg = tags + b*SEQ;
    const float* eb = em + b*SEQ*NTAG;

    for (int q = tid; q < NTAG*NTAG; q += 64){
        int i = q / NTAG, j = q - i*NTAG;
        tr[i*49 + j] = trans[q];
    }
    float part = 0.f;
    for (int t = tid; t < SEQ; t += 64){
        int tt = tg[t];
        part += eb[t*NTAG + tt];
        if (t < SEQ-1) part += trans[tt*NTAG + tg[t+1]];
    }
    red[tid] = part;
    if (tid < NTAG) al[0][tid] = start[tid] + eb[tid];
    __syncthreads();
    if (tid == 0){
        float s = 0.f;
        for (int i = 0; i < 64; i++) s += red[i];
        num_s = s + start[tg[0]] + endv[tg[SEQ-1]];
    }
    __syncthreads();

    for (int t = 1; t < SEQ; t++){
        int cur = t & 1, prv = cur ^ 1;
        float na = 0.f;
        if (tid < NTAG){
            float m = -1e30f;
            for (int i = 0; i < NTAG; i++) m = fmaxf(m, al[prv][i] + tr[i*49 + tid]);
            float ssum = 0.f;
            for (int i = 0; i < NTAG; i++) ssum += __expf(al[prv][i] + tr[i*49 + tid] - m);
            na = m + logf(ssum) + eb[t*NTAG + tid];
        }
        __syncthreads();
        if (tid < NTAG) al[cur][tid] = na;
        __syncthreads();
    }

    if (tid == 0){
        const float* a = al[(SEQ-1) & 1];
        float m = -1e30f;
        for (int j = 0; j < NTAG; j++) m = fmaxf(m, a[j] + endv[j]);
        float s = 0.f;
        for (int j = 0; j < NTAG; j++) s += __expf(a[j] + endv[j] - m);
        v[b] = num_s - (m + logf(s));
    }
}

__global__ void final_reduce(const float* __restrict__ v, float* __restrict__ out){
    __shared__ float s[64];
    s[threadIdx.x] = v[threadIdx.x];
    __syncthreads();
    if (threadIdx.x == 0){
        float a = 0.f;
        for (int i = 0; i < 64; i++) a += s[i];
        out[0] = -(a / 64.f);
    }
}

// ------------------- launch -------------------
extern "C" void kernel_launch(void* const* d_in, const int* in_sizes, int n_in,
                              void* d_out, int out_size)
{
    const float* inputs = (const float*)d_in[0];
    const int*   tags   = (const int*)d_in[1];
    const float *Wih0f=(const float*)d_in[2],  *Whh0f=(const float*)d_in[3],
                *bih0f=(const float*)d_in[4],  *bhh0f=(const float*)d_in[5];
    const float *Wih0b=(const float*)d_in[6],  *Whh0b=(const float*)d_in[7],
                *bih0b=(const float*)d_in[8],  *bhh0b=(const float*)d_in[9];
    const float *Wih1f=(const float*)d_in[10], *Whh1f=(const float*)d_in[11],
                *bih1f=(const float*)d_in[12], *bhh1f=(const float*)d_in[13];
    const float *Wih1b=(const float*)d_in[14], *Whh1b=(const float*)d_in[15],
                *bih1b=(const float*)d_in[16], *bhh1b=(const float*)d_in[17];
    const float *gamma=(const float*)d_in[18], *beta=(const float*)d_in[19],
                *mean=(const float*)d_in[20],  *var=(const float*)d_in[21];
    const float *fc1w=(const float*)d_in[22], *fc1b=(const float*)d_in[23];
    const float *fc2w=(const float*)d_in[24], *fc2b=(const float*)d_in[25];
    const float *fc3w=(const float*)d_in[26], *fc3b=(const float*)d_in[27];
    const float *crfS=(const float*)d_in[28], *crfE=(const float*)d_in[29],
                *crfT=(const float*)d_in[30];

    bf16 *pInb,*pW0m,*pW1m,*pWh0f,*pWh0b,*pWh1f,*pWh1b;
    bf16 *pFc1w,*pFc2w,*pFc3w,*pX1,*pX2,*pF1,*pF2,*pPre;
    float *pB0m,*pB1m,*pFc1b,*pEm,*pV;
    cudaGetSymbolAddress((void**)&pInb, d_inb);
    cudaGetSymbolAddress((void**)&pW0m, d_W0m);
    cudaGetSymbolAddress((void**)&pW1m, d_W1m);
    cudaGetSymbolAddress((void**)&pWh0f, d_Wh0f);
    cudaGetSymbolAddress((void**)&pWh0b, d_Wh0b);
    cudaGetSymbolAddress((void**)&pWh1f, d_Wh1f);
    cudaGetSymbolAddress((void**)&pWh1b, d_Wh1b);
    cudaGetSymbolAddress((void**)&pB0m, d_b0m);
    cudaGetSymbolAddress((void**)&pB1m, d_b1m);
    cudaGetSymbolAddress((void**)&pFc1w, d_fc1wP);
    cudaGetSymbolAddress((void**)&pFc1b, d_fc1bP);
    cudaGetSymbolAddress((void**)&pFc2w, d_fc2wB);
    cudaGetSymbolAddress((void**)&pFc3w, d_fc3wB);
    cudaGetSymbolAddress((void**)&pPre, d_pre);
    cudaGetSymbolAddress((void**)&pX1, d_x1);
    cudaGetSymbolAddress((void**)&pX2, d_x2);
    cudaGetSymbolAddress((void**)&pF1, d_f1);
    cudaGetSymbolAddress((void**)&pF2, d_f2);
    cudaGetSymbolAddress((void**)&pEm, d_em);
    cudaGetSymbolAddress((void**)&pV, d_v);

    const int gemm_smem = 2*2*128*BRS*2;
    const int lstm_smem = (2*64*WSB + 2*64*64)*2 + (64*68 + 64*16)*4;
    cudaFuncSetAttribute(gemm_bf16, cudaFuncAttributeMaxDynamicSharedMemorySize, gemm_smem);
    cudaFuncSetAttribute(lstm_layer, cudaFuncAttributeMaxDynamicSharedMemorySize, lstm_smem);

    prep_all<<<2048,256>>>(inputs, Wih0f, Wih0b, Whh0f, Whh0b, Wih1f, Wih1b, Whh1f, Whh1b,
                           bih0f, bhh0f, bih0b, bhh0b, bih1f, bhh1f, bih1b, bhh1b,
                           fc2w, fc3w);
    prep_fc<<<512,256>>>(fc1w, fc1b, gamma, beta, mean, var);
    gemm_bf16<<<dim3(32,128),256,gemm_smem>>>(pInb, pW0m, pB0m, pPre, MROWS, 4096, 256, 0, 1);
    lstm_layer<<<64,256,lstm_smem>>>(pPre, pWh0f, pWh0b, pX1, 0);
    gemm_bf16<<<dim3(32,128),256,gemm_smem>>>(pX1, pW1m, pB1m, pPre, MROWS, 4096, 1024, 0, 1);
    lstm_layer<<<64,256,lstm_smem>>>(pPre, pWh1f, pWh1b, pX2, 256);
    gemm_bf16<<<dim3(4,128),256,gemm_smem>>>(pX2, pFc1w, pFc1b, pF1, MROWS, 512, 1024, 1, 1);
    gemm_bf16<<<dim3(2,128),256,gemm_smem>>>(pF1, pFc2w, fc2b, pF2, MROWS, 256, 512, 1, 1);
    gemm_bf16<<<dim3(1,128),256,gemm_smem>>>(pF2, pFc3w, fc3b, pEm, MROWS, NTAG, 256, 0, 0);
    crf_kernel<<<64,64>>>(pEm, tags, crfS, crfE, crfT, pV);
    final_reduce<<<1,64>>>(pV, (float*)d_out);
}

// round 7
// speedup vs baseline: 3.8620x; 1.0562x over previous
#include <cuda_runtime.h>
#include <cuda_bf16.h>
#include <cstdint>

#define BATCH 64
#define SEQ   256
#define HID   512
#define NTAG  48
#define MROWS (BATCH*SEQ)     // 16384
#define G4    2048
#define H2    1024

typedef __nv_bfloat16 bf16;
typedef __nv_bfloat162 bf162;

// ------------------- static device scratch -------------------
__device__ bf16  d_inb[16384*256];
__device__ bf16  d_W0m[4096*256];
__device__ bf16  d_W1m[4096*1024];
__device__ bf16  d_Wh0f[2048*512];
__device__ bf16  d_Wh0b[2048*512];
__device__ bf16  d_Wh1f[2048*512];
__device__ bf16  d_Wh1b[2048*512];
__device__ float d_b0m[4096];
__device__ float d_b1m[4096];
__device__ bf16  d_fc1wP[512*1024];
__device__ float d_fc1bP[512];
__device__ bf16  d_fc2wB[256*512];
__device__ bf16  d_fc3wB[48*256];
__device__ bf16  d_pre[(size_t)16384*4096];
__device__ bf16  d_x1[16384*1024];
__device__ bf16  d_x2[16384*1024];
__device__ bf16  d_f1[16384*512];
__device__ bf16  d_f2[16384*256];
__device__ float d_em[16384*48];
__device__ bf16  d_hbuf[2*2*BATCH*HID];   // [parity][dir][b][j]
__device__ float d_v[64];
__device__ volatile int d_slot[2][512];   // slot ns at index ns*8 (32B stride)
__device__ volatile int d_genv[2];

// ------------------- helpers -------------------
__device__ __forceinline__ void mma16r(float* c,
    unsigned a0, unsigned a1, unsigned a2, unsigned a3, unsigned b0, unsigned b1){
    asm volatile(
        "mma.sync.aligned.m16n8k16.row.col.f32.bf16.bf16.f32 "
        "{%0,%1,%2,%3}, {%4,%5,%6,%7}, {%8,%9}, {%0,%1,%2,%3};\n"
        : "+f"(c[0]), "+f"(c[1]), "+f"(c[2]), "+f"(c[3])
        : "r"(a0), "r"(a1), "r"(a2), "r"(a3), "r"(b0), "r"(b1));
}

__device__ __forceinline__ void ldsm4(unsigned& r0, unsigned& r1, unsigned& r2, unsigned& r3,
                                      unsigned addr){
    asm volatile("ldmatrix.sync.aligned.m8n8.x4.shared.b16 {%0,%1,%2,%3}, [%4];"
        : "=r"(r0), "=r"(r1), "=r"(r2), "=r"(r3) : "r"(addr));
}

__device__ __forceinline__ float fsig(float x){
    float t;
    asm("mul.f32 %0, %1, 0fBFB8AA3B;" : "=f"(t) : "f"(x));
    asm("ex2.approx.f32 %0, %0;" : "+f"(t));
    asm("add.f32 %0, %0, 0f3F800000;" : "+f"(t));
    asm("rcp.approx.f32 %0, %0;" : "+f"(t));
    return t;
}
__device__ __forceinline__ float ftanh(float x){
    float r; asm("tanh.approx.f32 %0, %1;" : "=f"(r) : "f"(x)); return r;
}

__device__ __forceinline__ void cp16(void* smem, const void* gmem){
    unsigned sa = (unsigned)__cvta_generic_to_shared(smem);
    asm volatile("cp.async.cg.shared.global [%0], [%1], 16;" :: "r"(sa), "l"(gmem));
}
__device__ __forceinline__ void cp16z(void* smem, const void* gmem, int pred){
    unsigned sa = (unsigned)__cvta_generic_to_shared(smem);
    int bytes = pred ? 16 : 0;
    asm volatile("cp.async.cg.shared.global [%0], [%1], 16, %2;" :: "r"(sa), "l"(gmem), "r"(bytes));
}
__device__ __forceinline__ void cp_commit(){ asm volatile("cp.async.commit_group;"); }
__device__ __forceinline__ void cp_wait0(){ asm volatile("cp.async.wait_group 0;"); }
__device__ __forceinline__ void cp_wait1(){ asm volatile("cp.async.wait_group 1;"); }
__device__ __forceinline__ void cp_wait2(){ asm volatile("cp.async.wait_group 2;"); }

// ------------------- prep -------------------
__global__ void prep_all(
    const float* __restrict__ inputs,
    const float* __restrict__ Wih0f, const float* __restrict__ Wih0b,
    const float* __restrict__ Whh0f, const float* __restrict__ Whh0b,
    const float* __restrict__ Wih1f, const float* __restrict__ Wih1b,
    const float* __restrict__ Whh1f, const float* __restrict__ Whh1b,
    const float* __restrict__ bih0f, const float* __restrict__ bhh0f,
    const float* __restrict__ bih0b, const float* __restrict__ bhh0b,
    const float* __restrict__ bih1f, const float* __restrict__ bhh1f,
    const float* __restrict__ bih1b, const float* __restrict__ bhh1b,
    const float* __restrict__ fc2w, const float* __restrict__ fc3w)
{
    const int NIN = 16384*256;
    const int NW0 = 4096*256;
    const int NW1 = 4096*1024;
    const int NWH = 2048*512;
    const int e0 = NIN;
    const int e1 = e0 + NW0;
    const int e2 = e1 + NW1;
    const int e3 = e2 + 4*NWH;
    const int e4 = e3 + 4096;
    const int e5 = e4 + 4096;
    const int e6 = e5 + 256*512;
    const int e7 = e6 + 48*256;
    const int total = e7 + 1026;        // ctrl: 1024 slots + 2 genv
    int stride = gridDim.x * blockDim.x;
    for (int i = blockIdx.x*blockDim.x + threadIdx.x; i < total; i += stride){
        if (i < e0){
            d_inb[i] = __float2bfloat16_rn(inputs[i]);
        } else if (i < e1){
            int j = i - e0;
            int np = j >> 8, k = j & 255;
            int np2 = np & 2047;
            int sr = (np2 & 3)*512 + (np2 >> 2);
            const float* src = (np < 2048) ? Wih0f : Wih0b;
            d_W0m[j] = __float2bfloat16_rn(src[sr*256 + k]);
        } else if (i < e2){
            int j = i - e1;
            int np = j >> 10, k = j & 1023;
            int np2 = np & 2047;
            int sr = (np2 & 3)*512 + (np2 >> 2);
            const float* src = (np < 2048) ? Wih1f : Wih1b;
            d_W1m[j] = __float2bfloat16_rn(src[sr*1024 + k]);
        } else if (i < e3){
            int j = i - e2;
            int arr = j / NWH;
            int jj = j - arr*NWH;
            int np = jj >> 9, k = jj & 511;
            int sr = (np & 3)*512 + (np >> 2);
            const float* src = (arr==0)?Whh0f:(arr==1)?Whh0b:(arr==2)?Whh1f:Whh1b;
            bf16* dst = (arr==0)?d_Wh0f:(arr==1)?d_Wh0b:(arr==2)?d_Wh1f:d_Wh1b;
            dst[jj] = __float2bfloat16_rn(src[sr*512 + k]);
        } else if (i < e4){
            int np = i - e3;
            int np2 = np & 2047;
            int sr = (np2 & 3)*512 + (np2 >> 2);
            d_b0m[np] = (np < 2048) ? (bih0f[sr] + bhh0f[sr]) : (bih0b[sr] + bhh0b[sr]);
        } else if (i < e5){
            int np = i - e4;
            int np2 = np & 2047;
            int sr = (np2 & 3)*512 + (np2 >> 2);
            d_b1m[np] = (np < 2048) ? (bih1f[sr] + bhh1f[sr]) : (bih1b[sr] + bhh1b[sr]);
        } else if (i < e6){
            int j = i - e5;
            d_fc2wB[j] = __float2bfloat16_rn(fc2w[j]);
        } else if (i < e7){
            int j = i - e6;
            d_fc3wB[j] = __float2bfloat16_rn(fc3w[j]);
        } else {
            int j = i - e7;
            if (j < 1024) ((volatile int*)d_slot)[j] = 0;
            else d_genv[j - 1024] = 0;
        }
    }
}

// fold BN into fc1
__global__ void prep_fc(const float* __restrict__ fc1w, const float* __restrict__ fc1b,
                        const float* __restrict__ gamma, const float* __restrict__ beta,
                        const float* __restrict__ mean, const float* __restrict__ var)
{
    __shared__ float red[256];
    int r = blockIdx.x;
    int tid = threadIdx.x;
    float part = 0.f;
    for (int c = tid; c < 1024; c += 256){
        float sc = gamma[c] * rsqrtf(var[c] + 1e-5f);
        float tc = beta[c] - mean[c]*sc;
        float w = fc1w[r*1024 + c];
        d_fc1wP[r*1024 + c] = __float2bfloat16_rn(w * sc);
        part += w * tc;
    }
    red[tid] = part;
    __syncthreads();
    for (int off = 128; off > 0; off >>= 1){
        if (tid < off) red[tid] += red[tid + off];
        __syncthreads();
    }
    if (tid == 0) d_fc1bP[r] = fc1b[r] + red[0];
}

// ------------------- bf16 GEMM: C = A(MxK) @ W(NxK)^T + bias -------------------
#define BRS 40
__global__ __launch_bounds__(256) void gemm_bf16(
    const bf16* __restrict__ A, const bf16* __restrict__ W,
    const float* __restrict__ bias, void* __restrict__ Cv,
    int M, int N, int K, int relu, int outBf)
{
    extern __shared__ bf16 smb[];
    bf16* As = smb;
    bf16* Bs = smb + 2*128*BRS;
    int tid  = threadIdx.x;
    int warp = tid >> 5, lane = tid & 31;
    int wm = warp >> 2, wn = warp & 3;
    int g = lane >> 2, tg = lane & 3;
    int m0 = blockIdx.y*128, n0 = blockIdx.x*128;

    float acc[4][4][4];
#pragma unroll
    for (int a = 0; a < 4; a++)
#pragma unroll
        for (int b = 0; b < 4; b++)
#pragma unroll
            for (int c = 0; c < 4; c++) acc[a][b][c] = 0.f;

    int KT = K >> 5;

    auto stage = [&](int kt, int bb){
        const bf16* Ag = A + (size_t)m0*K + kt*32;
#pragma unroll
        for (int i = 0; i < 2; i++){
            int q = i*256 + tid;
            int r = q >> 2;
            int c = (q & 3) * 8;
            cp16(&As[bb*128*BRS + r*BRS + c], Ag + (size_t)r*K + c);
        }
        const bf16* Wg = W + kt*32;
#pragma unroll
        for (int i = 0; i < 2; i++){
            int q = i*256 + tid;
            int r = q >> 2;
            int c = (q & 3) * 8;
            int nr = n0 + r;
            int nc = nr < N ? nr : 0;
            cp16z(&Bs[bb*128*BRS + r*BRS + c], Wg + (size_t)nc*K + c, nr < N);
        }
        cp_commit();
    };

    stage(0, 0);
    if (KT > 1) stage(1, 1);

    for (int kt = 0; kt < KT; kt++){
        if (kt < KT-1) cp_wait1(); else cp_wait0();
        __syncthreads();
        int bb = kt & 1;
        const bf16* Ab = As + bb*128*BRS + (wm*64)*BRS;
        const bf16* Bb = Bs + bb*128*BRS + (wn*32)*BRS;
#pragma unroll
        for (int kk = 0; kk < 2; kk++){
            int kc = kk*16 + tg*2;
            unsigned af[4][4], bf[4][2];
#pragma unroll
            for (int mt = 0; mt < 4; mt++){
                const bf16* p = Ab + (mt*16 + g)*BRS + kc;
                af[mt][0] = *(const unsigned*)p;
                af[mt][1] = *(const unsigned*)(p + 8*BRS);
                af[mt][2] = *(const unsigned*)(p + 8);
                af[mt][3] = *(const unsigned*)(p + 8*BRS + 8);
            }
#pragma unroll
            for (int nt = 0; nt < 4; nt++){
                const bf16* p = Bb + (nt*8 + g)*BRS + kc;
                bf[nt][0] = *(const unsigned*)p;
                bf[nt][1] = *(const unsigned*)(p + 8);
            }
#pragma unroll
            for (int mt = 0; mt < 4; mt++)
#pragma unroll
                for (int nt = 0; nt < 4; nt++)
                    mma16r(acc[mt][nt], af[mt][0], af[mt][1], af[mt][2], af[mt][3],
                           bf[nt][0], bf[nt][1]);
        }
        __syncthreads();
        if (kt + 2 < KT) stage(kt+2, bb);
    }

#pragma unroll
    for (int mt = 0; mt < 4; mt++){
        int row = m0 + wm*64 + mt*16 + g;
#pragma unroll
        for (int nt = 0; nt < 4; nt++){
            int col = n0 + wn*32 + nt*8 + 2*tg;
            if (col < N){
                float b0 = bias[col], b1 = bias[col+1];
                float v0 = acc[mt][nt][0] + b0;
                float v1 = acc[mt][nt][1] + b1;
                float v2 = acc[mt][nt][2] + b0;
                float v3 = acc[mt][nt][3] + b1;
                if (relu){
                    v0 = fmaxf(v0, 0.f); v1 = fmaxf(v1, 0.f);
                    v2 = fmaxf(v2, 0.f); v3 = fmaxf(v3, 0.f);
                }
                if (outBf){
                    bf16* C16 = (bf16*)Cv;
                    *(bf162*)&C16[(size_t)row*N + col]     = __floats2bfloat162_rn(v0, v1);
                    *(bf162*)&C16[(size_t)(row+8)*N + col] = __floats2bfloat162_rn(v2, v3);
                } else {
                    float* C = (float*)Cv;
                    *(float2*)&C[(size_t)row*N + col]     = make_float2(v0, v1);
                    *(float2*)&C[(size_t)(row+8)*N + col] = make_float2(v2, v3);
                }
            }
        }
    }
}

// ------------------- persistent bidirectional LSTM layer -------------------
// 128 blocks x 256 threads. dir = bx>>6, ns = bx&63. Block owns gate cols [ns*32,+32)
// (gate-interleaved) = hidden units [ns*8,+8). 8 warps as 4(m) x 2(n), warp tile 16x16.
#define WSB 520
__global__ __launch_bounds__(256) void lstm_layer(
    const bf16* __restrict__ pre,
    const bf16* __restrict__ whhF, const bf16* __restrict__ whhB,
    bf16* __restrict__ out, int gen0)
{
    extern __shared__ char smraw[];
    bf16* whh_s = (bf16*)smraw;                  // [32][WSB]
    bf16* h_s   = whh_s + 32*WSB;                // [64][WSB]
    bf16* pre_s = h_s + 64*WSB;                  // [2][64][32]
    float* G_s  = (float*)(pre_s + 2*64*32);     // [64][36]
    float* c_s  = G_s + 64*36;                   // [64][8]

    int tid = threadIdx.x;
    int warp = tid >> 5, lane = tid & 31;
    int wm = warp >> 1, wn = warp & 1;
    int g = lane >> 2, tg = lane & 3;
    int dir = blockIdx.x >> 6;
    int ns  = blockIdx.x & 63;
    int n0  = ns*32;
    int j0  = ns*8;
    const bf16* whh = dir ? whhB : whhF;

    // persistent Whh slice: 32 gate rows x 512
#pragma unroll
    for (int i = 0; i < 8; i++){
        int q = i*256 + tid;
        int r = q >> 6;
        int c = (q & 63) * 8;
        cp16(&whh_s[r*WSB + c], &whh[(n0 + r)*512 + c]);
    }
    cp_commit();
    for (int q = tid; q < 64*8; q += 256) c_s[q] = 0.f;
    cp_wait0();
    __syncthreads();

    // ldmatrix lane addresses
    int lrow = lane & 15;
    int lcol = (lane >> 4) * 16;
    unsigned hbase = (unsigned)__cvta_generic_to_shared(h_s);
    unsigned wbase = (unsigned)__cvta_generic_to_shared(whh_s);
    unsigned aAddr = hbase + (unsigned)((wm*16 + lrow)*WSB)*2u + lcol;
    unsigned bAddr = wbase + (unsigned)((wn*16 + lrow)*WSB)*2u + lcol;

    int ub = tid >> 2;            // batch 0..63
    int uu = (tid & 3)*2;         // first of 2 units
    int pr_ = tid >> 2, pc_ = (tid & 3)*8;   // pre staging coords

    // prefetch pre for step 0
    {
        int t0 = dir ? (SEQ-1) : 0;
        cp16(&pre_s[pr_*32 + pc_], &pre[((size_t)(pr_*SEQ + t0))*4096 + dir*2048 + n0 + pc_]);
        cp_commit();
    }

    for (int s = 0; s < SEQ; s++){
        int t  = dir ? (SEQ-1 - s) : s;
        int rp = s & 1;
        int wp = rp ^ 1;

        if (s > 0){
            const bf16* hsrc = d_hbuf + (size_t)(rp*2 + dir)*BATCH*HID;
            // chunk 0: k cols [0,256)
#pragma unroll
            for (int i = 0; i < 8; i++){
                int q = i*256 + tid;
                int r = q >> 5;
                int c = (q & 31) * 8;
                cp16(&h_s[r*WSB + c], &hsrc[r*HID + c]);
            }
            cp_commit();
            // chunk 1: k cols [256,512)
#pragma unroll
            for (int i = 0; i < 8; i++){
                int q = i*256 + tid;
                int r = q >> 5;
                int c = (q & 31) * 8 + 256;
                cp16(&h_s[r*WSB + c], &hsrc[r*HID + c]);
            }
            cp_commit();
        }
        // prefetch pre for step s+1
        {
            int sn = s + 1;
            if (sn < SEQ){
                int tn = dir ? (SEQ-1 - sn) : sn;
                bf16* pb = pre_s + (sn & 1)*2048;
                cp16(&pb[pr_*32 + pc_], &pre[((size_t)(pr_*SEQ + tn))*4096 + dir*2048 + n0 + pc_]);
            }
            cp_commit();
        }

        float acc[2][4];
#pragma unroll
        for (int b = 0; b < 2; b++)
#pragma unroll
            for (int c = 0; c < 4; c++) acc[b][c] = 0.f;

        if (s > 0){
            cp_wait2();             // h chunk0 ready (and pre(s) from last iter)
            __syncthreads();
#pragma unroll 8
            for (int k16 = 0; k16 < 16; k16++){
                unsigned off = (unsigned)k16 * 32u;
                unsigned a0,a1,a2,a3, b0,b1,b2,b3;
                ldsm4(a0,a1,a2,a3, aAddr + off);
                ldsm4(b0,b1,b2,b3, bAddr + off);
                mma16r(acc[0], a0,a1,a2,a3, b0,b2);
                mma16r(acc[1], a0,a1,a2,a3, b1,b3);
            }
            cp_wait1();             // h chunk1 ready
            __syncthreads();
#pragma unroll 8
            for (int k16 = 16; k16 < 32; k16++){
                unsigned off = (unsigned)k16 * 32u;
                unsigned a0,a1,a2,a3, b0,b1,b2,b3;
                ldsm4(a0,a1,a2,a3, aAddr + off);
                ldsm4(b0,b1,b2,b3, bAddr + off);
                mma16r(acc[0], a0,a1,a2,a3, b0,b2);
                mma16r(acc[1], a0,a1,a2,a3, b1,b3);
            }
        } else {
            cp_wait1();             // pre(0) ready
        }

        // dump accumulators (rows = batch, cols = gate)
        {
            int rr = wm*16 + g;
#pragma unroll
            for (int nt = 0; nt < 2; nt++){
                int cc = wn*16 + nt*8 + 2*tg;
                G_s[rr*36 + cc]        = acc[nt][0];
                G_s[rr*36 + cc + 1]    = acc[nt][1];
                G_s[(rr+8)*36 + cc]    = acc[nt][2];
                G_s[(rr+8)*36 + cc+1]  = acc[nt][3];
            }
        }
        __syncthreads();

        // gate update: thread -> batch ub, units uu..uu+1
        {
            const bf16* pcur = pre_s + (s & 1)*2048;
            bf16* hdst = d_hbuf + (size_t)(wp*2 + dir)*BATCH*HID;
            float hv2[2];
#pragma unroll
            for (int k = 0; k < 2; k++){
                int u = uu + k;
                float4 Gv = *(float4*)&G_s[ub*36 + 4*u];
                bf162 pA = *(bf162*)&pcur[ub*32 + 4*u];
                bf162 pB = *(bf162*)&pcur[ub*32 + 4*u + 2];
                float iv = Gv.x + __low2float(pA);
                float fv = Gv.y + __high2float(pA);
                float gv = Gv.z + __low2float(pB);
                float ov = Gv.w + __high2float(pB);
                float co = c_s[ub*8 + u];
                float cn = fsig(fv)*co + fsig(iv)*ftanh(gv);
                hv2[k] = fsig(ov)*ftanh(cn);
                c_s[ub*8 + u] = cn;
            }
            bf162 p0 = __floats2bfloat162_rn(hv2[0], hv2[1]);
            unsigned pk = *(unsigned*)&p0;
            *(unsigned*)&hdst[ub*HID + j0 + uu] = pk;
            *(unsigned*)&out[(size_t)(ub*SEQ + t)*H2 + dir*HID + j0 + uu] = pk;
        }

        // one-hop per-direction barrier (64 slots, 2 polling warps)
        __syncthreads();
        int target = gen0 + s + 1;
        if (tid == 0){
            __threadfence();
            d_slot[dir][ns*8] = target;
        }
        if (tid < 64){
            while (d_slot[dir][tid*8] < target) { }
        }
        __syncthreads();
    }
}

// ------------------- CRF -------------------
__global__ void crf_kernel(const float* __restrict__ em, const int* __restrict__ tags,
                           const float* __restrict__ start, const float* __restrict__ endv,
                           const float* __restrict__ trans, float* __restrict__ v)
{
    __shared__ float tr[NTAG*49];
    __shared__ float al[2][NTAG];
    __shared__ float red[64];
    __shared__ float num_s;
    int b = blockIdx.x;
    int tid = threadIdx.x;
    const int* tg = tags + b*SEQ;
    const float* eb = em + b*SEQ*NTAG;

    for (int q = tid; q < NTAG*NTAG; q += 64){
        int i = q / NTAG, j = q - i*NTAG;
        tr[i*49 + j] = trans[q];
    }
    float part = 0.f;
    for (int t = tid; t < SEQ; t += 64){
        int tt = tg[t];
        part += eb[t*NTAG + tt];
        if (t < SEQ-1) part += trans[tt*NTAG + tg[t+1]];
    }
    red[tid] = part;
    if (tid < NTAG) al[0][tid] = start[tid] + eb[tid];
    __syncthreads();
    if (tid == 0){
        float s = 0.f;
        for (int i = 0; i < 64; i++) s += red[i];
        num_s = s + start[tg[0]] + endv[tg[SEQ-1]];
    }
    __syncthreads();

    for (int t = 1; t < SEQ; t++){
        int cur = t & 1, prv = cur ^ 1;
        float na = 0.f;
        if (tid < NTAG){
            float m = -1e30f;
            for (int i = 0; i < NTAG; i++) m = fmaxf(m, al[prv][i] + tr[i*49 + tid]);
            float ssum = 0.f;
            for (int i = 0; i < NTAG; i++) ssum += __expf(al[prv][i] + tr[i*49 + tid] - m);
            na = m + logf(ssum) + eb[t*NTAG + tid];
        }
        __syncthreads();
        if (tid < NTAG) al[cur][tid] = na;
        __syncthreads();
    }

    if (tid == 0){
        const float* a = al[(SEQ-1) & 1];
        float m = -1e30f;
        for (int j = 0; j < NTAG; j++) m = fmaxf(m, a[j] + endv[j]);
        float s = 0.f;
        for (int j = 0; j < NTAG; j++) s += __expf(a[j] + endv[j] - m);
        v[b] = num_s - (m + logf(s));
    }
}

__global__ void final_reduce(const float* __restrict__ v, float* __restrict__ out){
    __shared__ float s[64];
    s[threadIdx.x] = v[threadIdx.x];
    __syncthreads();
    if (threadIdx.x == 0){
        float a = 0.f;
        for (int i = 0; i < 64; i++) a += s[i];
        out[0] = -(a / 64.f);
    }
}

// ------------------- launch -------------------
extern "C" void kernel_launch(void* const* d_in, const int* in_sizes, int n_in,
                              void* d_out, int out_size)
{
    const float* inputs = (const float*)d_in[0];
    const int*   tags   = (const int*)d_in[1];
    const float *Wih0f=(const float*)d_in[2],  *Whh0f=(const float*)d_in[3],
                *bih0f=(const float*)d_in[4],  *bhh0f=(const float*)d_in[5];
    const float *Wih0b=(const float*)d_in[6],  *Whh0b=(const float*)d_in[7],
                *bih0b=(const float*)d_in[8],  *bhh0b=(const float*)d_in[9];
    const float *Wih1f=(const float*)d_in[10], *Whh1f=(const float*)d_in[11],
                *bih1f=(const float*)d_in[12], *bhh1f=(const float*)d_in[13];
    const float *Wih1b=(const float*)d_in[14], *Whh1b=(const float*)d_in[15],
                *bih1b=(const float*)d_in[16], *bhh1b=(const float*)d_in[17];
    const float *gamma=(const float*)d_in[18], *beta=(const float*)d_in[19],
                *mean=(const float*)d_in[20],  *var=(const float*)d_in[21];
    const float *fc1w=(const float*)d_in[22], *fc1b=(const float*)d_in[23];
    const float *fc2w=(const float*)d_in[24], *fc2b=(const float*)d_in[25];
    const float *fc3w=(const float*)d_in[26], *fc3b=(const float*)d_in[27];
    const float *crfS=(const float*)d_in[28], *crfE=(const float*)d_in[29],
                *crfT=(const float*)d_in[30];

    bf16 *pInb,*pW0m,*pW1m,*pWh0f,*pWh0b,*pWh1f,*pWh1b;
    bf16 *pFc1w,*pFc2w,*pFc3w,*pX1,*pX2,*pF1,*pF2,*pPre;
    float *pB0m,*pB1m,*pFc1b,*pEm,*pV;
    cudaGetSymbolAddress((void**)&pInb, d_inb);
    cudaGetSymbolAddress((void**)&pW0m, d_W0m);
    cudaGetSymbolAddress((void**)&pW1m, d_W1m);
    cudaGetSymbolAddress((void**)&pWh0f, d_Wh0f);
    cudaGetSymbolAddress((void**)&pWh0b, d_Wh0b);
    cudaGetSymbolAddress((void**)&pWh1f, d_Wh1f);
    cudaGetSymbolAddress((void**)&pWh1b, d_Wh1b);
    cudaGetSymbolAddress((void**)&pB0m, d_b0m);
    cudaGetSymbolAddress((void**)&pB1m, d_b1m);
    cudaGetSymbolAddress((void**)&pFc1w, d_fc1wP);
    cudaGetSymbolAddress((void**)&pFc1b, d_fc1bP);
    cudaGetSymbolAddress((void**)&pFc2w, d_fc2wB);
    cudaGetSymbolAddress((void**)&pFc3w, d_fc3wB);
    cudaGetSymbolAddress((void**)&pPre, d_pre);
    cudaGetSymbolAddress((void**)&pX1, d_x1);
    cudaGetSymbolAddress((void**)&pX2, d_x2);
    cudaGetSymbolAddress((void**)&pF1, d_f1);
    cudaGetSymbolAddress((void**)&pF2, d_f2);
    cudaGetSymbolAddress((void**)&pEm, d_em);
    cudaGetSymbolAddress((void**)&pV, d_v);

    const int gemm_smem = 2*2*128*BRS*2;
    const int lstm_smem = (32*WSB + 64*WSB + 2*64*32)*2 + (64*36 + 64*8)*4;
    cudaFuncSetAttribute(gemm_bf16, cudaFuncAttributeMaxDynamicSharedMemorySize, gemm_smem);
    cudaFuncSetAttribute(lstm_layer, cudaFuncAttributeMaxDynamicSharedMemorySize, lstm_smem);

    prep_all<<<2048,256>>>(inputs, Wih0f, Wih0b, Whh0f, Whh0b, Wih1f, Wih1b, Whh1f, Whh1b,
                           bih0f, bhh0f, bih0b, bhh0b, bih1f, bhh1f, bih1b, bhh1b,
                           fc2w, fc3w);
    prep_fc<<<512,256>>>(fc1w, fc1b, gamma, beta, mean, var);
    gemm_bf16<<<dim3(32,128),256,gemm_smem>>>(pInb, pW0m, pB0m, pPre, MROWS, 4096, 256, 0, 1);
    lstm_layer<<<128,256,lstm_smem>>>(pPre, pWh0f, pWh0b, pX1, 0);
    gemm_bf16<<<dim3(32,128),256,gemm_smem>>>(pX1, pW1m, pB1m, pPre, MROWS, 4096, 1024, 0, 1);
    lstm_layer<<<128,256,lstm_smem>>>(pPre, pWh1f, pWh1b, pX2, 256);
    gemm_bf16<<<dim3(4,128),256,gemm_smem>>>(pX2, pFc1w, pFc1b, pF1, MROWS, 512, 1024, 1, 1);
    gemm_bf16<<<dim3(2,128),256,gemm_smem>>>(pF1, pFc2w, fc2b, pF2, MROWS, 256, 512, 1, 1);
    gemm_bf16<<<dim3(1,128),256,gemm_smem>>>(pF2, pFc3w, fc3b, pEm, MROWS, NTAG, 256, 0, 0);
    crf_kernel<<<64,64>>>(pEm, tags, crfS, crfE, crfT, pV);
    final_reduce<<<1,64>>>(pV, (float*)d_out);
}

// round 9
// speedup vs baseline: 4.0925x; 1.0597x over previous
#include <cuda_runtime.h>
#include <cuda_bf16.h>
#include <cstdint>

#define BATCH 64
#define SEQ   256
#define HID   512
#define NTAG  48
#define MROWS (BATCH*SEQ)     // 16384
#define G4    2048
#define H2    1024

typedef __nv_bfloat16 bf16;
typedef __nv_bfloat162 bf162;

// ------------------- static device scratch -------------------
__device__ bf16  d_inb[16384*256];
__device__ bf16  d_W0m[4096*256];
__device__ bf16  d_W1m[4096*1024];
__device__ bf16  d_Wh0f[2048*512];
__device__ bf16  d_Wh0b[2048*512];
__device__ bf16  d_Wh1f[2048*512];
__device__ bf16  d_Wh1b[2048*512];
__device__ float d_b0m[4096];
__device__ float d_b1m[4096];
__device__ bf16  d_fc1wP[512*1024];
__device__ float d_fc1bP[512];
__device__ bf16  d_fc2wB[256*512];
__device__ bf16  d_fc3wB[48*256];
__device__ bf16  d_pre[(size_t)16384*4096];
__device__ bf16  d_x1[16384*1024];
__device__ bf16  d_x2[16384*1024];
__device__ bf16  d_f1[16384*512];
__device__ bf16  d_f2[16384*256];
__device__ float d_em[16384*48];
__device__ bf16  d_hbuf[2*2*BATCH*HID];   // [parity][dir][b][j]
__device__ float d_v[64];
__device__ int   d_slot[2][512];          // slot ns at index ns*8 (32B stride)

// ------------------- helpers -------------------
__device__ __forceinline__ void mma16r(float* c,
    unsigned a0, unsigned a1, unsigned a2, unsigned a3, unsigned b0, unsigned b1){
    asm volatile(
        "mma.sync.aligned.m16n8k16.row.col.f32.bf16.bf16.f32 "
        "{%0,%1,%2,%3}, {%4,%5,%6,%7}, {%8,%9}, {%0,%1,%2,%3};\n"
        : "+f"(c[0]), "+f"(c[1]), "+f"(c[2]), "+f"(c[3])
        : "r"(a0), "r"(a1), "r"(a2), "r"(a3), "r"(b0), "r"(b1));
}

__device__ __forceinline__ void ldsm4(unsigned& r0, unsigned& r1, unsigned& r2, unsigned& r3,
                                      unsigned addr){
    asm volatile("ldmatrix.sync.aligned.m8n8.x4.shared.b16 {%0,%1,%2,%3}, [%4];"
        : "=r"(r0), "=r"(r1), "=r"(r2), "=r"(r3) : "r"(addr));
}

__device__ __forceinline__ float fsig(float x){
    float t;
    asm("mul.f32 %0, %1, 0fBFB8AA3B;" : "=f"(t) : "f"(x));
    asm("ex2.approx.f32 %0, %0;" : "+f"(t));
    asm("add.f32 %0, %0, 0f3F800000;" : "+f"(t));
    asm("rcp.approx.f32 %0, %0;" : "+f"(t));
    return t;
}
__device__ __forceinline__ float ftanh(float x){
    float r; asm("tanh.approx.f32 %0, %1;" : "=f"(r) : "f"(x)); return r;
}

__device__ __forceinline__ void st_release(int* addr, int v){
    asm volatile("st.release.gpu.global.s32 [%0], %1;" :: "l"(addr), "r"(v) : "memory");
}
__device__ __forceinline__ int ld_acquire(const int* addr){
    int v;
    asm volatile("ld.acquire.gpu.global.s32 %0, [%1];" : "=r"(v) : "l"(addr) : "memory");
    return v;
}

__device__ __forceinline__ void cp16(void* smem, const void* gmem){
    unsigned sa = (unsigned)__cvta_generic_to_shared(smem);
    asm volatile("cp.async.cg.shared.global [%0], [%1], 16;" :: "r"(sa), "l"(gmem));
}
__device__ __forceinline__ void cp16z(void* smem, const void* gmem, int pred){
    unsigned sa = (unsigned)__cvta_generic_to_shared(smem);
    int bytes = pred ? 16 : 0;
    asm volatile("cp.async.cg.shared.global [%0], [%1], 16, %2;" :: "r"(sa), "l"(gmem), "r"(bytes));
}
__device__ __forceinline__ void cp_commit(){ asm volatile("cp.async.commit_group;"); }
__device__ __forceinline__ void cp_wait0(){ asm volatile("cp.async.wait_group 0;"); }
__device__ __forceinline__ void cp_wait1(){ asm volatile("cp.async.wait_group 1;"); }
__device__ __forceinline__ void cp_wait2(){ asm volatile("cp.async.wait_group 2;"); }

// ------------------- prep -------------------
__global__ void prep_all(
    const float* __restrict__ inputs,
    const float* __restrict__ Wih0f, const float* __restrict__ Wih0b,
    const float* __restrict__ Whh0f, const float* __restrict__ Whh0b,
    const float* __restrict__ Wih1f, const float* __restrict__ Wih1b,
    const float* __restrict__ Whh1f, const float* __restrict__ Whh1b,
    const float* __restrict__ bih0f, const float* __restrict__ bhh0f,
    const float* __restrict__ bih0b, const float* __restrict__ bhh0b,
    const float* __restrict__ bih1f, const float* __restrict__ bhh1f,
    const float* __restrict__ bih1b, const float* __restrict__ bhh1b,
    const float* __restrict__ fc2w, const float* __restrict__ fc3w)
{
    const int NIN = 16384*256;
    const int NW0 = 4096*256;
    const int NW1 = 4096*1024;
    const int NWH = 2048*512;
    const int e0 = NIN;
    const int e1 = e0 + NW0;
    const int e2 = e1 + NW1;
    const int e3 = e2 + 4*NWH;
    const int e4 = e3 + 4096;
    const int e5 = e4 + 4096;
    const int e6 = e5 + 256*512;
    const int e7 = e6 + 48*256;
    const int total = e7 + 1024;        // ctrl: 1024 slots
    int stride = gridDim.x * blockDim.x;
    for (int i = blockIdx.x*blockDim.x + threadIdx.x; i < total; i += stride){
        if (i < e0){
            d_inb[i] = __float2bfloat16_rn(inputs[i]);
        } else if (i < e1){
            int j = i - e0;
            int np = j >> 8, k = j & 255;
            int np2 = np & 2047;
            int sr = (np2 & 3)*512 + (np2 >> 2);
            const float* src = (np < 2048) ? Wih0f : Wih0b;
            d_W0m[j] = __float2bfloat16_rn(src[sr*256 + k]);
        } else if (i < e2){
            int j = i - e1;
            int np = j >> 10, k = j & 1023;
            int np2 = np & 2047;
            int sr = (np2 & 3)*512 + (np2 >> 2);
            const float* src = (np < 2048) ? Wih1f : Wih1b;
            d_W1m[j] = __float2bfloat16_rn(src[sr*1024 + k]);
        } else if (i < e3){
            int j = i - e2;
            int arr = j / NWH;
            int jj = j - arr*NWH;
            int np = jj >> 9, k = jj & 511;
            int sr = (np & 3)*512 + (np >> 2);
            const float* src = (arr==0)?Whh0f:(arr==1)?Whh0b:(arr==2)?Whh1f:Whh1b;
            bf16* dst = (arr==0)?d_Wh0f:(arr==1)?d_Wh0b:(arr==2)?d_Wh1f:d_Wh1b;
            dst[jj] = __float2bfloat16_rn(src[sr*512 + k]);
        } else if (i < e4){
            int np = i - e3;
            int np2 = np & 2047;
            int sr = (np2 & 3)*512 + (np2 >> 2);
            d_b0m[np] = (np < 2048) ? (bih0f[sr] + bhh0f[sr]) : (bih0b[sr] + bhh0b[sr]);
        } else if (i < e5){
            int np = i - e4;
            int np2 = np & 2047;
            int sr = (np2 & 3)*512 + (np2 >> 2);
            d_b1m[np] = (np < 2048) ? (bih1f[sr] + bhh1f[sr]) : (bih1b[sr] + bhh1b[sr]);
        } else if (i < e6){
            int j = i - e5;
            d_fc2wB[j] = __float2bfloat16_rn(fc2w[j]);
        } else if (i < e7){
            int j = i - e6;
            d_fc3wB[j] = __float2bfloat16_rn(fc3w[j]);
        } else {
            ((int*)d_slot)[i - e7] = 0;
        }
    }
}

// fold BN into fc1
__global__ void prep_fc(const float* __restrict__ fc1w, const float* __restrict__ fc1b,
                        const float* __restrict__ gamma, const float* __restrict__ beta,
                        const float* __restrict__ mean, const float* __restrict__ var)
{
    __shared__ float red[256];
    int r = blockIdx.x;
    int tid = threadIdx.x;
    float part = 0.f;
    for (int c = tid; c < 1024; c += 256){
        float sc = gamma[c] * rsqrtf(var[c] + 1e-5f);
        float tc = beta[c] - mean[c]*sc;
        float w = fc1w[r*1024 + c];
        d_fc1wP[r*1024 + c] = __float2bfloat16_rn(w * sc);
        part += w * tc;
    }
    red[tid] = part;
    __syncthreads();
    for (int off = 128; off > 0; off >>= 1){
        if (tid < off) red[tid] += red[tid + off];
        __syncthreads();
    }
    if (tid == 0) d_fc1bP[r] = fc1b[r] + red[0];
}

// ------------------- bf16 GEMM: C = A(MxK) @ W(NxK)^T + bias -------------------
#define BRS 40
__global__ __launch_bounds__(256) void gemm_bf16(
    const bf16* __restrict__ A, const bf16* __restrict__ W,
    const float* __restrict__ bias, void* __restrict__ Cv,
    int M, int N, int K, int relu, int outBf)
{
    extern __shared__ bf16 smb[];
    bf16* As = smb;
    bf16* Bs = smb + 2*128*BRS;
    int tid  = threadIdx.x;
    int warp = tid >> 5, lane = tid & 31;
    int wm = warp >> 2, wn = warp & 3;
    int g = lane >> 2, tg = lane & 3;
    int m0 = blockIdx.y*128, n0 = blockIdx.x*128;

    float acc[4][4][4];
#pragma unroll
    for (int a = 0; a < 4; a++)
#pragma unroll
        for (int b = 0; b < 4; b++)
#pragma unroll
            for (int c = 0; c < 4; c++) acc[a][b][c] = 0.f;

    int KT = K >> 5;

    auto stage = [&](int kt, int bb){
        const bf16* Ag = A + (size_t)m0*K + kt*32;
#pragma unroll
        for (int i = 0; i < 2; i++){
            int q = i*256 + tid;
            int r = q >> 2;
            int c = (q & 3) * 8;
            cp16(&As[bb*128*BRS + r*BRS + c], Ag + (size_t)r*K + c);
        }
        const bf16* Wg = W + kt*32;
#pragma unroll
        for (int i = 0; i < 2; i++){
            int q = i*256 + tid;
            int r = q >> 2;
            int c = (q & 3) * 8;
            int nr = n0 + r;
            int nc = nr < N ? nr : 0;
            cp16z(&Bs[bb*128*BRS + r*BRS + c], Wg + (size_t)nc*K + c, nr < N);
        }
        cp_commit();
    };

    stage(0, 0);
    if (KT > 1) stage(1, 1);

    for (int kt = 0; kt < KT; kt++){
        if (kt < KT-1) cp_wait1(); else cp_wait0();
        __syncthreads();
        int bb = kt & 1;
        const bf16* Ab = As + bb*128*BRS + (wm*64)*BRS;
        const bf16* Bb = Bs + bb*128*BRS + (wn*32)*BRS;
#pragma unroll
        for (int kk = 0; kk < 2; kk++){
            int kc = kk*16 + tg*2;
            unsigned af[4][4], bf[4][2];
#pragma unroll
            for (int mt = 0; mt < 4; mt++){
                const bf16* p = Ab + (mt*16 + g)*BRS + kc;
                af[mt][0] = *(const unsigned*)p;
                af[mt][1] = *(const unsigned*)(p + 8*BRS);
                af[mt][2] = *(const unsigned*)(p + 8);
                af[mt][3] = *(const unsigned*)(p + 8*BRS + 8);
            }
#pragma unroll
            for (int nt = 0; nt < 4; nt++){
                const bf16* p = Bb + (nt*8 + g)*BRS + kc;
                bf[nt][0] = *(const unsigned*)p;
                bf[nt][1] = *(const unsigned*)(p + 8);
            }
#pragma unroll
            for (int mt = 0; mt < 4; mt++)
#pragma unroll
                for (int nt = 0; nt < 4; nt++)
                    mma16r(acc[mt][nt], af[mt][0], af[mt][1], af[mt][2], af[mt][3],
                           bf[nt][0], bf[nt][1]);
        }
        __syncthreads();
        if (kt + 2 < KT) stage(kt+2, bb);
    }

#pragma unroll
    for (int mt = 0; mt < 4; mt++){
        int row = m0 + wm*64 + mt*16 + g;
#pragma unroll
        for (int nt = 0; nt < 4; nt++){
            int col = n0 + wn*32 + nt*8 + 2*tg;
            if (col < N){
                float b0 = bias[col], b1 = bias[col+1];
                float v0 = acc[mt][nt][0] + b0;
                float v1 = acc[mt][nt][1] + b1;
                float v2 = acc[mt][nt][2] + b0;
                float v3 = acc[mt][nt][3] + b1;
                if (relu){
                    v0 = fmaxf(v0, 0.f); v1 = fmaxf(v1, 0.f);
                    v2 = fmaxf(v2, 0.f); v3 = fmaxf(v3, 0.f);
                }
                if (outBf){
                    bf16* C16 = (bf16*)Cv;
                    *(bf162*)&C16[(size_t)row*N + col]     = __floats2bfloat162_rn(v0, v1);
                    *(bf162*)&C16[(size_t)(row+8)*N + col] = __floats2bfloat162_rn(v2, v3);
                } else {
                    float* C = (float*)Cv;
                    *(float2*)&C[(size_t)row*N + col]     = make_float2(v0, v1);
                    *(float2*)&C[(size_t)(row+8)*N + col] = make_float2(v2, v3);
                }
            }
        }
    }
}

// ------------------- persistent bidirectional LSTM layer -------------------
// 128 blocks x 256 threads. dir = bx>>6, ns = bx&63. Block owns gate cols [ns*32,+32)
// (gate-interleaved) = hidden units [ns*8,+8). 8 warps as 4(m) x 2(n), warp tile 16x16.
#define WSB 520
__global__ __launch_bounds__(256) void lstm_layer(
    const bf16* __restrict__ pre,
    const bf16* __restrict__ whhF, const bf16* __restrict__ whhB,
    bf16* __restrict__ out, int gen0)
{
    extern __shared__ char smraw[];
    bf16* whh_s = (bf16*)smraw;                  // [32][WSB]
    bf16* h_s   = whh_s + 32*WSB;                // [64][WSB]
    bf16* pre_s = h_s + 64*WSB;                  // [2][64][32]
    float* G_s  = (float*)(pre_s + 2*64*32);     // [64][36]
    float* c_s  = G_s + 64*36;                   // [64][8]

    int tid = threadIdx.x;
    int warp = tid >> 5, lane = tid & 31;
    int wm = warp >> 1, wn = warp & 1;
    int g = lane >> 2, tg = lane & 3;
    int dir = blockIdx.x >> 6;
    int ns  = blockIdx.x & 63;
    int n0  = ns*32;
    int j0  = ns*8;
    const bf16* whh = dir ? whhB : whhF;
    int* slots = &d_slot[dir][0];

    // persistent Whh slice: 32 gate rows x 512
#pragma unroll
    for (int i = 0; i < 8; i++){
        int q = i*256 + tid;
        int r = q >> 6;
        int c = (q & 63) * 8;
        cp16(&whh_s[r*WSB + c], &whh[(n0 + r)*512 + c]);
    }
    cp_commit();
    for (int q = tid; q < 64*8; q += 256) c_s[q] = 0.f;
    cp_wait0();
    __syncthreads();

    // ldmatrix lane addresses
    int lrow = lane & 15;
    int lcol = (lane >> 4) * 16;
    unsigned hbase = (unsigned)__cvta_generic_to_shared(h_s);
    unsigned wbase = (unsigned)__cvta_generic_to_shared(whh_s);
    unsigned aAddr = hbase + (unsigned)((wm*16 + lrow)*WSB)*2u + lcol;
    unsigned bAddr = wbase + (unsigned)((wn*16 + lrow)*WSB)*2u + lcol;

    int ub = tid >> 2;            // batch 0..63
    int uu = (tid & 3)*2;         // first of 2 units
    int pr_ = tid >> 2, pc_ = (tid & 3)*8;   // pre staging coords

    // prefetch pre for step 0
    {
        int t0 = dir ? (SEQ-1) : 0;
        cp16(&pre_s[pr_*32 + pc_], &pre[((size_t)(pr_*SEQ + t0))*4096 + dir*2048 + n0 + pc_]);
        cp_commit();
    }

    for (int s = 0; s < SEQ; s++){
        int t  = dir ? (SEQ-1 - s) : s;
        int rp = s & 1;
        int wp = rp ^ 1;

        if (s > 0){
            const bf16* hsrc = d_hbuf + (size_t)(rp*2 + dir)*BATCH*HID;
#pragma unroll
            for (int i = 0; i < 8; i++){
                int q = i*256 + tid;
                int r = q >> 5;
                int c = (q & 31) * 8;
                cp16(&h_s[r*WSB + c], &hsrc[r*HID + c]);
            }
            cp_commit();
#pragma unroll
            for (int i = 0; i < 8; i++){
                int q = i*256 + tid;
                int r = q >> 5;
                int c = (q & 31) * 8 + 256;
                cp16(&h_s[r*WSB + c], &hsrc[r*HID + c]);
            }
            cp_commit();
        }
        // prefetch pre for step s+1
        {
            int sn = s + 1;
            if (sn < SEQ){
                int tn = dir ? (SEQ-1 - sn) : sn;
                bf16* pb = pre_s + (sn & 1)*2048;
                cp16(&pb[pr_*32 + pc_], &pre[((size_t)(pr_*SEQ + tn))*4096 + dir*2048 + n0 + pc_]);
            }
            cp_commit();
        }

        float acc[2][4];
#pragma unroll
        for (int b = 0; b < 2; b++)
#pragma unroll
            for (int c = 0; c < 4; c++) acc[b][c] = 0.f;

        if (s > 0){
            cp_wait2();
            __syncthreads();
#pragma unroll 8
            for (int k16 = 0; k16 < 16; k16++){
                unsigned off = (unsigned)k16 * 32u;
                unsigned a0,a1,a2,a3, b0,b1,b2,b3;
                ldsm4(a0,a1,a2,a3, aAddr + off);
                ldsm4(b0,b1,b2,b3, bAddr + off);
                mma16r(acc[0], a0,a1,a2,a3, b0,b2);
                mma16r(acc[1], a0,a1,a2,a3, b1,b3);
            }
            cp_wait1();
            __syncthreads();
#pragma unroll 8
            for (int k16 = 16; k16 < 32; k16++){
                unsigned off = (unsigned)k16 * 32u;
                unsigned a0,a1,a2,a3, b0,b1,b2,b3;
                ldsm4(a0,a1,a2,a3, aAddr + off);
                ldsm4(b0,b1,b2,b3, bAddr + off);
                mma16r(acc[0], a0,a1,a2,a3, b0,b2);
                mma16r(acc[1], a0,a1,a2,a3, b1,b3);
            }
        } else {
            cp_wait1();
        }

        // dump accumulators (rows = batch, cols = gate)
        {
            int rr = wm*16 + g;
#pragma unroll
            for (int nt = 0; nt < 2; nt++){
                int cc = wn*16 + nt*8 + 2*tg;
                G_s[rr*36 + cc]        = acc[nt][0];
                G_s[rr*36 + cc + 1]    = acc[nt][1];
                G_s[(rr+8)*36 + cc]    = acc[nt][2];
                G_s[(rr+8)*36 + cc+1]  = acc[nt][3];
            }
        }
        __syncthreads();

        // gate update: thread -> batch ub, units uu..uu+1
        unsigned pk;
        {
            const bf16* pcur = pre_s + (s & 1)*2048;
            bf16* hdst = d_hbuf + (size_t)(wp*2 + dir)*BATCH*HID;
            float hv2[2];
#pragma unroll
            for (int k = 0; k < 2; k++){
                int u = uu + k;
                float4 Gv = *(float4*)&G_s[ub*36 + 4*u];
                bf162 pA = *(bf162*)&pcur[ub*32 + 4*u];
                bf162 pB = *(bf162*)&pcur[ub*32 + 4*u + 2];
                float iv = Gv.x + __low2float(pA);
                float fv = Gv.y + __high2float(pA);
                float gv = Gv.z + __low2float(pB);
                float ov = Gv.w + __high2float(pB);
                float co = c_s[ub*8 + u];
                float cn = fsig(fv)*co + fsig(iv)*ftanh(gv);
                hv2[k] = fsig(ov)*ftanh(cn);
                c_s[ub*8 + u] = cn;
            }
            bf162 p0 = __floats2bfloat162_rn(hv2[0], hv2[1]);
            pk = *(unsigned*)&p0;
            *(unsigned*)&hdst[ub*HID + j0 + uu] = pk;   // critical store only
        }

        // one-hop per-direction barrier: release -> (out store overlaps poll) -> acquire
        __syncthreads();
        int target = gen0 + s + 1;
        if (tid == 0){
            st_release(&slots[ns*8], target);
        }
        // out store is off the critical path: no other block reads it
        *(unsigned*)&out[(size_t)(ub*SEQ + t)*H2 + dir*HID + j0 + uu] = pk;
        if (tid < 64){
            while (ld_acquire(&slots[tid*8]) < target) { }
        }
        __syncthreads();
    }
}

// ------------------- CRF: alpha' = m + log(exp(alpha-m) @ exp(T)) + em -------------------
__global__ void crf_kernel(const float* __restrict__ em, const int* __restrict__ tags,
                           const float* __restrict__ start, const float* __restrict__ endv,
                           const float* __restrict__ trans, float* __restrict__ v)
{
    __shared__ float E[NTAG*49];     // exp(trans)
    __shared__ float al[NTAG];
    __shared__ float p[NTAG];
    __shared__ float red[64];
    __shared__ float num_s;
    int b = blockIdx.x;
    int tid = threadIdx.x;
    const int* tg = tags + b*SEQ;
    const float* eb = em + b*SEQ*NTAG;

    for (int q = tid; q < NTAG*NTAG; q += 64){
        int i = q / NTAG, j = q - i*NTAG;
        E[i*49 + j] = __expf(trans[q]);
    }
    float part = 0.f;
    for (int t = tid; t < SEQ; t += 64){
        int tt = tg[t];
        part += eb[t*NTAG + tt];
        if (t < SEQ-1) part += trans[tt*NTAG + tg[t+1]];
    }
    red[tid] = part;
    if (tid < NTAG) al[tid] = start[tid] + eb[tid];
    __syncthreads();
    if (tid == 0){
        float s = 0.f;
        for (int i = 0; i < 64; i++) s += red[i];
        num_s = s + start[tg[0]] + endv[tg[SEQ-1]];
    }
    __syncthreads();

    for (int t = 1; t < SEQ; t++){
        // p_i = exp(al_i - al_0); al spread is O(1) so this is well-conditioned
        if (tid < NTAG) p[tid] = __expf(al[tid] - al[0]);
        __syncthreads();
        float na = 0.f;
        if (tid < NTAG){
            float m0 = al[0];
            float ssum = 0.f;
#pragma unroll 8
            for (int i = 0; i < NTAG; i++) ssum += p[i] * E[i*49 + tid];
            na = m0 + __logf(ssum) + eb[t*NTAG + tid];
        }
        __syncthreads();
        if (tid < NTAG) al[tid] = na;
        __syncthreads();
    }

    if (tid == 0){
        float m = -1e30f;
        for (int j = 0; j < NTAG; j++) m = fmaxf(m, al[j] + endv[j]);
        float s = 0.f;
        for (int j = 0; j < NTAG; j++) s += __expf(al[j] + endv[j] - m);
        v[b] = num_s - (m + __logf(s));
    }
}

__global__ void final_reduce(const float* __restrict__ v, float* __restrict__ out){
    __shared__ float s[64];
    s[threadIdx.x] = v[threadIdx.x];
    __syncthreads();
    if (threadIdx.x == 0){
        float a = 0.f;
        for (int i = 0; i < 64; i++) a += s[i];
        out[0] = -(a / 64.f);
    }
}

// ------------------- launch -------------------
extern "C" void kernel_launch(void* const* d_in, const int* in_sizes, int n_in,
                              void* d_out, int out_size)
{
    const float* inputs = (const float*)d_in[0];
    const int*   tags   = (const int*)d_in[1];
    const float *Wih0f=(const float*)d_in[2],  *Whh0f=(const float*)d_in[3],
                *bih0f=(const float*)d_in[4],  *bhh0f=(const float*)d_in[5];
    const float *Wih0b=(const float*)d_in[6],  *Whh0b=(const float*)d_in[7],
                *bih0b=(const float*)d_in[8],  *bhh0b=(const float*)d_in[9];
    const float *Wih1f=(const float*)d_in[10], *Whh1f=(const float*)d_in[11],
                *bih1f=(const float*)d_in[12], *bhh1f=(const float*)d_in[13];
    const float *Wih1b=(const float*)d_in[14], *Whh1b=(const float*)d_in[15],
                *bih1b=(const float*)d_in[16], *bhh1b=(const float*)d_in[17];
    const float *gamma=(const float*)d_in[18], *beta=(const float*)d_in[19],
                *mean=(const float*)d_in[20],  *var=(const float*)d_in[21];
    const float *fc1w=(const float*)d_in[22], *fc1b=(const float*)d_in[23];
    const float *fc2w=(const float*)d_in[24], *fc2b=(const float*)d_in[25];
    const float *fc3w=(const float*)d_in[26], *fc3b=(const float*)d_in[27];
    const float *crfS=(const float*)d_in[28], *crfE=(const float*)d_in[29],
                *crfT=(const float*)d_in[30];

    bf16 *pInb,*pW0m,*pW1m,*pWh0f,*pWh0b,*pWh1f,*pWh1b;
    bf16 *pFc1w,*pFc2w,*pFc3w,*pX1,*pX2,*pF1,*pF2,*pPre;
    float *pB0m,*pB1m,*pFc1b,*pEm,*pV;
    cudaGetSymbolAddress((void**)&pInb, d_inb);
    cudaGetSymbolAddress((void**)&pW0m, d_W0m);
    cudaGetSymbolAddress((void**)&pW1m, d_W1m);
    cudaGetSymbolAddress((void**)&pWh0f, d_Wh0f);
    cudaGetSymbolAddress((void**)&pWh0b, d_Wh0b);
    cudaGetSymbolAddress((void**)&pWh1f, d_Wh1f);
    cudaGetSymbolAddress((void**)&pWh1b, d_Wh1b);
    cudaGetSymbolAddress((void**)&pB0m, d_b0m);
    cudaGetSymbolAddress((void**)&pB1m, d_b1m);
    cudaGetSymbolAddress((void**)&pFc1w, d_fc1wP);
    cudaGetSymbolAddress((void**)&pFc1b, d_fc1bP);
    cudaGetSymbolAddress((void**)&pFc2w, d_fc2wB);
    cudaGetSymbolAddress((void**)&pFc3w, d_fc3wB);
    cudaGetSymbolAddress((void**)&pPre, d_pre);
    cudaGetSymbolAddress((void**)&pX1, d_x1);
    cudaGetSymbolAddress((void**)&pX2, d_x2);
    cudaGetSymbolAddress((void**)&pF1, d_f1);
    cudaGetSymbolAddress((void**)&pF2, d_f2);
    cudaGetSymbolAddress((void**)&pEm, d_em);
    cudaGetSymbolAddress((void**)&pV, d_v);

    const int gemm_smem = 2*2*128*BRS*2;
    const int lstm_smem = (32*WSB + 64*WSB + 2*64*32)*2 + (64*36 + 64*8)*4;
    cudaFuncSetAttribute(gemm_bf16, cudaFuncAttributeMaxDynamicSharedMemorySize, gemm_smem);
    cudaFuncSetAttribute(lstm_layer, cudaFuncAttributeMaxDynamicSharedMemorySize, lstm_smem);

    prep_all<<<2048,256>>>(inputs, Wih0f, Wih0b, Whh0f, Whh0b, Wih1f, Wih1b, Whh1f, Whh1b,
                           bih0f, bhh0f, bih0b, bhh0b, bih1f, bhh1f, bih1b, bhh1b,
                           fc2w, fc3w);
    prep_fc<<<512,256>>>(fc1w, fc1b, gamma, beta, mean, var);
    gemm_bf16<<<dim3(32,128),256,gemm_smem>>>(pInb, pW0m, pB0m, pPre, MROWS, 4096, 256, 0, 1);
    lstm_layer<<<128,256,lstm_smem>>>(pPre, pWh0f, pWh0b, pX1, 0);
    gemm_bf16<<<dim3(32,128),256,gemm_smem>>>(pX1, pW1m, pB1m, pPre, MROWS, 4096, 1024, 0, 1);
    lstm_layer<<<128,256,lstm_smem>>>(pPre, pWh1f, pWh1b, pX2, 256);
    gemm_bf16<<<dim3(4,128),256,gemm_smem>>>(pX2, pFc1w, pFc1b, pF1, MROWS, 512, 1024, 1, 1);
    gemm_bf16<<<dim3(2,128),256,gemm_smem>>>(pF1, pFc2w, fc2b, pF2, MROWS, 256, 512, 1, 1);
    gemm_bf16<<<dim3(1,128),256,gemm_smem>>>(pF2, pFc3w, fc3b, pEm, MROWS, NTAG, 256, 0, 0);
    crf_kernel<<<64,64>>>(pEm, tags, crfS, crfE, crfT, pV);
    final_reduce<<<1,64>>>(pV, (float*)d_out);
}